// round 3
// baseline (speedup 1.0000x reference)
#include <cuda_runtime.h>
#include <math.h>

// ---------------- problem constants ----------------
#define BB    2
#define LL    4096
#define DD    512
#define HH    8
#define DHD   64
#define MM    266
#define MP    288            // padded feature dim (9*32)
#define NROWS (BB*LL)        // 8192
#define CHUNK 64
#define NCH   (LL/CHUNK)     // 64
#define BHT   (BB*HH)        // 16

#define INV_S4      0.21022410381342863f   // 512^-0.25
#define INV_SQRT512 0.04419417382415922f   // 512^-0.5

// ---------------- scratch (device globals; cudaMalloc is banned) ----------------
__device__ float g_Q[NROWS*DD];
__device__ float g_K[NROWS*DD];
__device__ float g_V[NROWS*DD];
__device__ float g_hq[NROWS*HH];
__device__ float g_hk[NROWS*HH];
__device__ float g_qp[(size_t)BHT*LL*MP];              // [b][h][l][m]  (m padded, zeros >=266)
__device__ float g_kp[(size_t)BHT*LL*MP];
__device__ float g_S [(size_t)BHT*NCH*MP*DHD];         // [bh][c][m][d]
__device__ float g_z [(size_t)BHT*NCH*MP];             // [bh][c][m]
__device__ float g_ctx[NROWS*DD];

// ---------------- SGEMM 128x128, BK=8, 8x8 microtile, double-buffered ----------------
__global__ void __launch_bounds__(256, 2)
sgemm128(const float* __restrict__ A0, const float* __restrict__ W0,
         const float* __restrict__ b0, float* __restrict__ C0,
         const float* __restrict__ A1, const float* __restrict__ W1,
         const float* __restrict__ b1, float* __restrict__ C1,
         const float* __restrict__ A2, const float* __restrict__ W2,
         const float* __restrict__ b2, float* __restrict__ C2) {
    __shared__ float As[2][8][132];
    __shared__ float Ws[2][8][132];

    const float* A; const float* W; const float* bias; float* C;
    if (blockIdx.z == 0)      { A = A0; W = W0; bias = b0; C = C0; }
    else if (blockIdx.z == 1) { A = A1; W = W1; bias = b1; C = C1; }
    else                      { A = A2; W = W2; bias = b2; C = C2; }

    const int t = threadIdx.x;
    const int row0 = blockIdx.y * 128, col0 = blockIdx.x * 128;
    const int lr = t >> 1;
    const int lk = (t & 1) * 4;
    const int ty = t >> 4, tx = t & 15;

    float acc[8][8];
    #pragma unroll
    for (int i = 0; i < 8; i++)
        #pragma unroll
        for (int j = 0; j < 8; j++) acc[i][j] = 0.f;

    float4 aS = *(const float4*)&A[(size_t)(row0 + lr) * DD + lk];
    float4 wS = *(const float4*)&W[(size_t)(col0 + lr) * DD + lk];
    #pragma unroll
    for (int i = 0; i < 4; i++) {
        As[0][lk + i][lr] = ((const float*)&aS)[i];
        Ws[0][lk + i][lr] = ((const float*)&wS)[i];
    }
    __syncthreads();

    int buf = 0;
    for (int kt = 0; kt < DD / 8; kt++) {
        float4 aN, wN;
        if (kt < DD / 8 - 1) {
            int k0 = (kt + 1) * 8;
            aN = *(const float4*)&A[(size_t)(row0 + lr) * DD + k0 + lk];
            wN = *(const float4*)&W[(size_t)(col0 + lr) * DD + k0 + lk];
        }
        #pragma unroll
        for (int k = 0; k < 8; k++) {
            float4 a0 = *(float4*)&As[buf][k][ty * 8];
            float4 a1 = *(float4*)&As[buf][k][ty * 8 + 4];
            float4 w0 = *(float4*)&Ws[buf][k][tx * 8];
            float4 w1 = *(float4*)&Ws[buf][k][tx * 8 + 4];
            float a[8] = {a0.x,a0.y,a0.z,a0.w,a1.x,a1.y,a1.z,a1.w};
            float w[8] = {w0.x,w0.y,w0.z,w0.w,w1.x,w1.y,w1.z,w1.w};
            #pragma unroll
            for (int i = 0; i < 8; i++)
                #pragma unroll
                for (int j = 0; j < 8; j++) acc[i][j] += a[i] * w[j];
        }
        if (kt < DD / 8 - 1) {
            #pragma unroll
            for (int i = 0; i < 4; i++) {
                As[buf ^ 1][lk + i][lr] = ((const float*)&aN)[i];
                Ws[buf ^ 1][lk + i][lr] = ((const float*)&wN)[i];
            }
            __syncthreads();
            buf ^= 1;
        }
    }

    #pragma unroll
    for (int i = 0; i < 8; i++) {
        size_t r = row0 + ty * 8 + i;
        #pragma unroll
        for (int j = 0; j < 8; j += 4) {
            int cidx = col0 + tx * 8 + j;
            float4 o = make_float4(acc[i][j] + bias[cidx],
                                   acc[i][j+1] + bias[cidx+1],
                                   acc[i][j+2] + bias[cidx+2],
                                   acc[i][j+3] + bias[cidx+3]);
            *(float4*)&C[r * DD + cidx] = o;
        }
    }
}

// ---------------- per-(row,head) -0.5*||x/scale||^2 ----------------
__global__ void hq_kernel(const float* __restrict__ X, float* __restrict__ hout) {
    int row = blockIdx.x;
    int w = threadIdx.x >> 5, lane = threadIdx.x & 31;
    const float* xr = X + (size_t)row * DD + w * DHD;
    float2 v = *(const float2*)&xr[lane * 2];
    float s = v.x * v.x + v.y * v.y;
    #pragma unroll
    for (int off = 16; off; off >>= 1) s += __shfl_xor_sync(0xffffffffu, s, off);
    if (lane == 0) hout[(size_t)row * HH + w] = -0.5f * INV_SQRT512 * s;
}

// ---------------- feature map -> padded [bh][l][MP], zeros for m>=266 ----------------
__global__ void __launch_bounds__(256) feat_gemm(const float* __restrict__ X,
                                                 const float* __restrict__ RF,
                                                 const float* __restrict__ hv,
                                                 float* __restrict__ outp) {
    __shared__ float Xs[16][132];
    __shared__ float Rs[16][68];
    const int t = threadIdx.x;
    const int h  = blockIdx.z;
    const int r0 = blockIdx.y * 128;
    const int m0 = blockIdx.x * 64;
    const int ty = t >> 4, tx = t & 15;

    float acc[8][4];
    #pragma unroll
    for (int i = 0; i < 8; i++)
        #pragma unroll
        for (int j = 0; j < 4; j++) acc[i][j] = 0.f;

    const int xr = t & 127;
    const int xk = (t >> 7) * 8;
    const int rm = t & 63;
    const int rk = (t >> 6) * 4;

    for (int kc = 0; kc < DHD; kc += 16) {
        float4 x0 = *(const float4*)&X[(size_t)(r0 + xr) * DD + h * DHD + kc + xk];
        float4 x1 = *(const float4*)&X[(size_t)(r0 + xr) * DD + h * DHD + kc + xk + 4];
        #pragma unroll
        for (int i = 0; i < 4; i++) {
            Xs[xk + i][xr]     = ((const float*)&x0)[i] * INV_S4;
            Xs[xk + 4 + i][xr] = ((const float*)&x1)[i] * INV_S4;
        }
        int mg = m0 + rm;
        float4 rv = make_float4(0.f, 0.f, 0.f, 0.f);
        if (mg < MM) rv = *(const float4*)&RF[(size_t)mg * DHD + kc + rk];
        #pragma unroll
        for (int i = 0; i < 4; i++) Rs[rk + i][rm] = ((const float*)&rv)[i];
        __syncthreads();

        #pragma unroll
        for (int k = 0; k < 16; k++) {
            float4 a0 = *(float4*)&Xs[k][ty * 8];
            float4 a1 = *(float4*)&Xs[k][ty * 8 + 4];
            float4 bb = *(float4*)&Rs[k][tx * 4];
            float a[8] = {a0.x,a0.y,a0.z,a0.w,a1.x,a1.y,a1.z,a1.w};
            float w[4] = {bb.x,bb.y,bb.z,bb.w};
            #pragma unroll
            for (int i = 0; i < 8; i++)
                #pragma unroll
                for (int j = 0; j < 4; j++) acc[i][j] += a[i] * w[j];
        }
        __syncthreads();
    }

    #pragma unroll
    for (int i = 0; i < 8; i++) {
        int r = r0 + ty * 8 + i;
        float hval = hv[(size_t)r * HH + h];
        int b = r >> 12, l = r & 4095;
        size_t base = (((size_t)(b * HH + h)) * LL + l) * MP;
        #pragma unroll
        for (int j = 0; j < 4; j++) {
            int m = m0 + tx * 4 + j;
            if (m < MP) outp[base + m] = (m < MM) ? expf(acc[i][j] + hval) : 0.f;
        }
    }
}

// ---------------- phase A: per-chunk S_c[m][d] = sum_t k'[t][m] v[t][d] ----------------
// grid (5, NCH, BHT), block 256. m-tile 64 (last tile half-valid), 4x4 microtile.
__global__ void __launch_bounds__(256) phaseA_kernel() {
    __shared__ float ks[16][68];
    __shared__ float vs[16][68];
    const int tid = threadIdx.x;
    const int tx = tid & 15, ty = tid >> 4;
    const int m0 = blockIdx.x * 64;
    const int c = blockIdx.y;
    const int bh = blockIdx.z;
    const int b = bh >> 3, h = bh & 7;
    const int l0 = c * CHUNK;
    const float* kb = g_kp + ((size_t)bh * LL + l0) * MP + m0;
    const float* vb = g_V + ((size_t)(b * LL + l0)) * DD + h * DHD;

    const int lt = tid >> 4;            // 0..15 t
    const int lm4 = (tid & 15) * 4;     // 0..60

    float acc[4][4];
    #pragma unroll
    for (int i = 0; i < 4; i++)
        #pragma unroll
        for (int j = 0; j < 4; j++) acc[i][j] = 0.f;

    for (int t0 = 0; t0 < CHUNK; t0 += 16) {
        float4 kv = make_float4(0.f, 0.f, 0.f, 0.f);
        if (m0 + lm4 < MP) kv = *(const float4*)&kb[(size_t)(t0 + lt) * MP + lm4];
        *(float4*)&ks[lt][lm4] = kv;
        *(float4*)&vs[lt][lm4] = *(const float4*)&vb[(size_t)(t0 + lt) * DD + lm4];
        __syncthreads();
        #pragma unroll
        for (int t = 0; t < 16; t++) {
            float4 a4 = *(float4*)&ks[t][ty * 4];
            float4 v4 = *(float4*)&vs[t][tx * 4];
            float a[4] = {a4.x, a4.y, a4.z, a4.w};
            float v[4] = {v4.x, v4.y, v4.z, v4.w};
            #pragma unroll
            for (int i = 0; i < 4; i++)
                #pragma unroll
                for (int j = 0; j < 4; j++) acc[i][j] += a[i] * v[j];
        }
        __syncthreads();
    }
    int m = m0 + ty * 4;
    if (m < MP) {
        float* Sb = g_S + ((size_t)bh * NCH + c) * (MP * DHD);
        #pragma unroll
        for (int i = 0; i < 4; i++) {
            float4 o = make_float4(acc[i][0], acc[i][1], acc[i][2], acc[i][3]);
            *(float4*)&Sb[(size_t)(m + i) * DHD + tx * 4] = o;
        }
    }
}

// ---------------- z: z_c[m] = sum_t k'[t][m] ----------------
__global__ void z_kernel() {
    const int m = threadIdx.x;            // 0..287
    const int c = blockIdx.x, bh = blockIdx.y;
    const float* kb = g_kp + ((size_t)bh * LL + c * CHUNK) * MP + m;
    float s = 0.f;
    #pragma unroll 8
    for (int t = 0; t < CHUNK; t++) s += kb[(size_t)t * MP];
    g_z[((size_t)bh * NCH + c) * MP + m] = s;
}

// ---------------- exclusive prefix over chunks ----------------
__global__ void scan_kernel(float* data, int per) {
    int gid = blockIdx.x * blockDim.x + threadIdx.x;
    if (gid >= BHT * per) return;
    int bh = gid / per, e = gid % per;
    size_t base = (size_t)bh * NCH * per + e;
    float run = 0.f;
    #pragma unroll 4
    for (int c = 0; c < NCH; c++) {
        size_t idx = base + (size_t)c * per;
        float cur = data[idx];
        data[idx] = run;
        run += cur;
    }
}

// ---------------- phase C: fused [A | inter] GEMM + A*V + epilogue ----------------
// grid (NCH, HH, BB), block 256.
__global__ void __launch_bounds__(256) phaseC_kernel() {
    __shared__ float sm_p1[6560];        // Qs[32][68] | Bs[32][136] | zs[32]; later Vs[64][68]
    __shared__ float A_sh[64][68];
    __shared__ float denq[64];

    float (*Qs)[68]  = (float(*)[68])sm_p1;            // 2176 floats
    float (*Bs)[136] = (float(*)[136])(sm_p1 + 2176);  // 4352 floats
    float* zs        = sm_p1 + 6528;                    // 32 floats
    float (*Vs)[68]  = (float(*)[68])sm_p1;            // aliased after main loop

    const int tid = threadIdx.x;
    const int tx = tid & 15, ty = tid >> 4;
    const int c = blockIdx.x, h = blockIdx.y, b = blockIdx.z;
    const int bh = b * HH + h;
    const int l0 = c * CHUNK;
    const float* qrow = g_qp + ((size_t)bh * LL + l0) * MP;
    const float* krow = g_kp + ((size_t)bh * LL + l0) * MP;
    const float* Srow = g_S + ((size_t)bh * NCH + c) * (MP * DHD);
    const float* zrow = g_z + ((size_t)bh * NCH + c) * MP;

    float acc[4][8];
    float dq[4];
    #pragma unroll
    for (int i = 0; i < 4; i++) {
        dq[i] = 0.f;
        #pragma unroll
        for (int j = 0; j < 8; j++) acc[i][j] = 0.f;
    }

    // staging thread mapping
    const int st  = tid >> 2;            // 0..63 (t or s)
    const int smj = (tid & 3) * 8;       // m offset 0,8,16,24
    const int sm2 = tid >> 3;            // 0..31 (m for S rows)
    const int sd8 = (tid & 7) * 8;       // d offset 0..56

    for (int kc = 0; kc < MP / 32; kc++) {
        const int m0k = kc * 32;
        // Q' transposed staging: Qs[m][t]
        {
            float4 q0 = *(const float4*)&qrow[(size_t)st * MP + m0k + smj];
            float4 q1 = *(const float4*)&qrow[(size_t)st * MP + m0k + smj + 4];
            #pragma unroll
            for (int i = 0; i < 4; i++) {
                Qs[smj + i][st]     = ((const float*)&q0)[i];
                Qs[smj + 4 + i][st] = ((const float*)&q1)[i];
            }
            // K' transposed staging: Bs[m][s]
            float4 k0 = *(const float4*)&krow[(size_t)st * MP + m0k + smj];
            float4 k1 = *(const float4*)&krow[(size_t)st * MP + m0k + smj + 4];
            #pragma unroll
            for (int i = 0; i < 4; i++) {
                Bs[smj + i][st]     = ((const float*)&k0)[i];
                Bs[smj + 4 + i][st] = ((const float*)&k1)[i];
            }
            // S staging (natural): Bs[m][64+d]
            float4 s0 = *(const float4*)&Srow[(size_t)(m0k + sm2) * DHD + sd8];
            float4 s1 = *(const float4*)&Srow[(size_t)(m0k + sm2) * DHD + sd8 + 4];
            *(float4*)&Bs[sm2][64 + sd8]     = s0;
            *(float4*)&Bs[sm2][64 + sd8 + 4] = s1;
            if (tid < 32) zs[tid] = zrow[m0k + tid];
        }
        __syncthreads();
        #pragma unroll 4
        for (int k = 0; k < 32; k++) {
            float4 a4 = *(float4*)&Qs[k][ty * 4];
            float4 b0 = *(float4*)&Bs[k][tx * 8];
            float4 b1 = *(float4*)&Bs[k][tx * 8 + 4];
            float z = zs[k];
            float a[4] = {a4.x, a4.y, a4.z, a4.w};
            float w[8] = {b0.x,b0.y,b0.z,b0.w,b1.x,b1.y,b1.z,b1.w};
            #pragma unroll
            for (int i = 0; i < 4; i++) {
                #pragma unroll
                for (int j = 0; j < 8; j++) acc[i][j] += a[i] * w[j];
                dq[i] += a[i] * z;
            }
        }
        __syncthreads();
    }

    // split outputs: tx<8 -> masked A into smem; tx>=8 -> inter into g_ctx (staging)
    if (tx < 8) {
        #pragma unroll
        for (int i = 0; i < 4; i++) {
            int t = ty * 4 + i;
            #pragma unroll
            for (int j = 0; j < 8; j++) {
                int s = tx * 8 + j;
                A_sh[t][s] = (s <= t) ? acc[i][j] : 0.f;
            }
        }
    } else {
        #pragma unroll
        for (int i = 0; i < 4; i++) {
            int t = ty * 4 + i;
            int d = (tx - 8) * 8;
            float* dst = &g_ctx[((size_t)(b * LL + l0 + t)) * DD + h * DHD + d];
            *(float4*)dst       = make_float4(acc[i][0], acc[i][1], acc[i][2], acc[i][3]);
            *(float4*)(dst + 4) = make_float4(acc[i][4], acc[i][5], acc[i][6], acc[i][7]);
        }
    }
    if (tx == 0) {
        #pragma unroll
        for (int i = 0; i < 4; i++) denq[ty * 4 + i] = dq[i];
    }
    __syncthreads();

    // load V chunk into aliased region
    {
        const int vs_s = tid >> 2;
        const int vdj = (tid & 3) * 16;
        const float* vsrc = &g_V[((size_t)(b * LL + l0 + vs_s)) * DD + h * DHD + vdj];
        #pragma unroll
        for (int q = 0; q < 4; q++)
            *(float4*)&Vs[vs_s][vdj + q * 4] = *(const float4*)&vsrc[q * 4];
    }
    __syncthreads();

    // gemm2: num = A_masked * V (K=64), den2 = rowsum(A_masked)
    float num[4][4];
    float den2[4];
    #pragma unroll
    for (int i = 0; i < 4; i++) {
        den2[i] = 0.f;
        #pragma unroll
        for (int j = 0; j < 4; j++) num[i][j] = 0.f;
    }
    #pragma unroll 4
    for (int s = 0; s < 64; s++) {
        float a[4];
        #pragma unroll
        for (int i = 0; i < 4; i++) a[i] = A_sh[ty * 4 + i][s];
        float4 v4 = *(float4*)&Vs[s][tx * 4];
        float v[4] = {v4.x, v4.y, v4.z, v4.w};
        #pragma unroll
        for (int i = 0; i < 4; i++) {
            #pragma unroll
            for (int j = 0; j < 4; j++) num[i][j] += a[i] * v[j];
            den2[i] += a[i];
        }
    }

    // epilogue: ctx = (num + inter)/den
    #pragma unroll
    for (int i = 0; i < 4; i++) {
        int t = ty * 4 + i;
        float inv = 1.0f / (den2[i] + denq[t]);
        float* dst = &g_ctx[((size_t)(b * LL + l0 + t)) * DD + h * DHD + tx * 4];
        float4 inter = *(float4*)dst;
        float4 o = make_float4((num[i][0] + inter.x) * inv,
                               (num[i][1] + inter.y) * inv,
                               (num[i][2] + inter.z) * inv,
                               (num[i][3] + inter.w) * inv);
        *(float4*)dst = o;
    }
}

// ---------------- launch ----------------
extern "C" void kernel_launch(void* const* d_in, const int* in_sizes, int n_in,
                              void* d_out, int out_size) {
    const float* query = (const float*)d_in[0];
    const float* key   = (const float*)d_in[1];
    const float* value = (const float*)d_in[2];
    const float* Wq    = (const float*)d_in[3];
    const float* bq    = (const float*)d_in[4];
    const float* Wk    = (const float*)d_in[5];
    const float* bk    = (const float*)d_in[6];
    const float* Wv    = (const float*)d_in[7];
    const float* bv    = (const float*)d_in[8];
    const float* Wout  = (const float*)d_in[9];
    const float* bout  = (const float*)d_in[10];
    const float* RF    = (const float*)d_in[11];

    float *Qp, *Kp, *Vp, *hqp, *hkp, *qpp, *kpp, *Sp, *zp, *ctxp;
    cudaGetSymbolAddress((void**)&Qp,  g_Q);
    cudaGetSymbolAddress((void**)&Kp,  g_K);
    cudaGetSymbolAddress((void**)&Vp,  g_V);
    cudaGetSymbolAddress((void**)&hqp, g_hq);
    cudaGetSymbolAddress((void**)&hkp, g_hk);
    cudaGetSymbolAddress((void**)&qpp, g_qp);
    cudaGetSymbolAddress((void**)&kpp, g_kp);
    cudaGetSymbolAddress((void**)&Sp,  g_S);
    cudaGetSymbolAddress((void**)&zp,  g_z);
    cudaGetSymbolAddress((void**)&ctxp, g_ctx);

    dim3 gp(DD / 128, NROWS / 128, 3);
    sgemm128<<<gp, 256>>>(query, Wq, bq, Qp,
                          key,   Wk, bk, Kp,
                          value, Wv, bv, Vp);

    hq_kernel<<<NROWS, 256>>>(Qp, hqp);
    hq_kernel<<<NROWS, 256>>>(Kp, hkp);

    dim3 fg(5, NROWS / 128, HH);               // m-tiles of 64 covering 320 (guarded)
    feat_gemm<<<fg, 256>>>(Qp, RF, hqp, qpp);
    feat_gemm<<<fg, 256>>>(Kp, RF, hkp, kpp);

    dim3 pa(5, NCH, BHT);
    phaseA_kernel<<<pa, 256>>>();

    dim3 zg(NCH, BHT);
    z_kernel<<<zg, MP>>>();

    int perS = MP * DHD;
    scan_kernel<<<(BHT * perS + 255) / 256, 256>>>(Sp, perS);
    scan_kernel<<<(BHT * MP + 255) / 256, 256>>>(zp, MP);

    dim3 pc(NCH, HH, BB);
    phaseC_kernel<<<pc, 256>>>();

    dim3 go(DD / 128, NROWS / 128, 1);
    sgemm128<<<go, 256>>>(ctxp, Wout, bout, (float*)d_out,
                          ctxp, Wout, bout, (float*)d_out,
                          ctxp, Wout, bout, (float*)d_out);
}

// round 4
// speedup vs baseline: 1.4172x; 1.4172x over previous
#include <cuda_runtime.h>
#include <math.h>
#include <stdint.h>

// ---------------- problem constants ----------------
#define BB    2
#define LL    4096
#define DD    512
#define HH    8
#define DHD   64
#define MM    266
#define NROWS (BB*LL)        // 8192
#define CHUNK 64
#define NCH   (LL/CHUNK)     // 64
#define BHT   (BB*HH)        // 16

#define INV_S4      0.21022410381342863f   // 512^-0.25
#define INV_SQRT512 0.04419417382415922f   // 512^-0.5

// ---------------- scratch ----------------
__device__ float g_Q[NROWS*DD];
__device__ float g_K[NROWS*DD];
__device__ float g_V[NROWS*DD];
__device__ float g_hq[NROWS*HH];
__device__ float g_hk[NROWS*HH];
__device__ float g_qp[(size_t)BHT*LL*MM];
__device__ float g_kp[(size_t)BHT*LL*MM];
__device__ float g_S [(size_t)BHT*NCH*MM*DHD];
__device__ float g_z [(size_t)BHT*NCH*MM];
__device__ float g_ctx[NROWS*DD];

// ---------------- TF32 helpers ----------------
__device__ __forceinline__ uint32_t f2tf(float f) {
    uint32_t u;
    asm("cvt.rna.tf32.f32 %0, %1;" : "=r"(u) : "f"(f));
    return u;
}
__device__ __forceinline__ void mma_tf32(float* c, const uint32_t* a,
                                         uint32_t b0, uint32_t b1) {
    asm volatile(
        "mma.sync.aligned.m16n8k8.row.col.f32.tf32.tf32.f32 "
        "{%0,%1,%2,%3}, {%4,%5,%6,%7}, {%8,%9}, {%0,%1,%2,%3};"
        : "+f"(c[0]), "+f"(c[1]), "+f"(c[2]), "+f"(c[3])
        : "r"(a[0]), "r"(a[1]), "r"(a[2]), "r"(a[3]), "r"(b0), "r"(b1));
}

// ---------------- TF32 GEMM: C[n,o] = A[n,:]·W[o,:] + bias[o] ----------------
// 128x128 block tile, 8 warps (4x2), warp tile 32x64, k-stage 32.
__global__ void __launch_bounds__(256, 2)
tf32_gemm(const float* __restrict__ A0, const float* __restrict__ W0,
          const float* __restrict__ bb0, float* __restrict__ C0,
          const float* __restrict__ A1, const float* __restrict__ W1,
          const float* __restrict__ bb1, float* __restrict__ C1,
          const float* __restrict__ A2, const float* __restrict__ W2,
          const float* __restrict__ bb2, float* __restrict__ C2) {
    __shared__ uint32_t As[128][36];
    __shared__ uint32_t Ws[128][36];

    const float* A; const float* W; const float* bias; float* C;
    if (blockIdx.z == 0)      { A = A0; W = W0; bias = bb0; C = C0; }
    else if (blockIdx.z == 1) { A = A1; W = W1; bias = bb1; C = C1; }
    else                      { A = A2; W = W2; bias = bb2; C = C2; }

    const int t = threadIdx.x;
    const int wid = t >> 5, lane = t & 31;
    const int warp_m = (wid & 3) * 32;
    const int warp_n = (wid >> 2) * 64;
    const int row0 = blockIdx.y * 128, col0 = blockIdx.x * 128;
    const int g = lane >> 2, tg = lane & 3;

    float c[2][8][4];
    #pragma unroll
    for (int f = 0; f < 2; f++)
        #pragma unroll
        for (int j = 0; j < 8; j++)
            #pragma unroll
            for (int q = 0; q < 4; q++) c[f][j][q] = 0.f;

    for (int ks = 0; ks < DD; ks += 32) {
        // stage 128x32 of A and W (tf32-converted)
        #pragma unroll
        for (int i = 0; i < 4; i++) {
            int idx = t + i * 256;
            int r = idx >> 3, q = idx & 7;
            float4 av = *(const float4*)&A[(size_t)(row0 + r) * DD + ks + q * 4];
            float4 wv = *(const float4*)&W[(size_t)(col0 + r) * DD + ks + q * 4];
            uint4 au = make_uint4(f2tf(av.x), f2tf(av.y), f2tf(av.z), f2tf(av.w));
            uint4 wu = make_uint4(f2tf(wv.x), f2tf(wv.y), f2tf(wv.z), f2tf(wv.w));
            *(uint4*)&As[r][q * 4] = au;
            *(uint4*)&Ws[r][q * 4] = wu;
        }
        __syncthreads();
        #pragma unroll
        for (int k8 = 0; k8 < 32; k8 += 8) {
            uint32_t a[2][4];
            #pragma unroll
            for (int f = 0; f < 2; f++) {
                int m0 = warp_m + 16 * f;
                a[f][0] = As[m0 + g][k8 + tg];
                a[f][1] = As[m0 + g + 8][k8 + tg];
                a[f][2] = As[m0 + g][k8 + tg + 4];
                a[f][3] = As[m0 + g + 8][k8 + tg + 4];
            }
            #pragma unroll
            for (int j = 0; j < 8; j++) {
                uint32_t b0 = Ws[warp_n + 8 * j + g][k8 + tg];
                uint32_t b1 = Ws[warp_n + 8 * j + g][k8 + tg + 4];
                mma_tf32(c[0][j], a[0], b0, b1);
                mma_tf32(c[1][j], a[1], b0, b1);
            }
        }
        __syncthreads();
    }

    // epilogue
    #pragma unroll
    for (int f = 0; f < 2; f++) {
        int r0 = row0 + warp_m + 16 * f + g;
        #pragma unroll
        for (int j = 0; j < 8; j++) {
            int cidx = col0 + warp_n + 8 * j + 2 * tg;
            float bx = bias[cidx], by = bias[cidx + 1];
            float2 o0 = make_float2(c[f][j][0] + bx, c[f][j][1] + by);
            float2 o1 = make_float2(c[f][j][2] + bx, c[f][j][3] + by);
            *(float2*)&C[(size_t)r0 * DD + cidx] = o0;
            *(float2*)&C[(size_t)(r0 + 8) * DD + cidx] = o1;
        }
    }
}

// ---------------- per-(row,head) -0.5*||x/scale||^2 ----------------
__global__ void hq_kernel(const float* __restrict__ X, float* __restrict__ hout) {
    int row = blockIdx.x;
    int w = threadIdx.x >> 5, lane = threadIdx.x & 31;
    const float* xr = X + (size_t)row * DD + w * DHD;
    float2 v = *(const float2*)&xr[lane * 2];
    float s = v.x * v.x + v.y * v.y;
    #pragma unroll
    for (int off = 16; off; off >>= 1) s += __shfl_xor_sync(0xffffffffu, s, off);
    if (lane == 0) hout[(size_t)row * HH + w] = -0.5f * INV_SQRT512 * s;
}

// ---------------- feature map (R2 version) ----------------
__global__ void __launch_bounds__(256) feat_gemm(const float* __restrict__ X,
                                                 const float* __restrict__ RF,
                                                 const float* __restrict__ hv,
                                                 float* __restrict__ outp) {
    __shared__ float Xs[16][132];
    __shared__ float Rs[16][68];
    const int t = threadIdx.x;
    const int h  = blockIdx.z;
    const int r0 = blockIdx.y * 128;
    const int m0 = blockIdx.x * 64;
    const int ty = t >> 4, tx = t & 15;

    float acc[8][4];
    #pragma unroll
    for (int i = 0; i < 8; i++)
        #pragma unroll
        for (int j = 0; j < 4; j++) acc[i][j] = 0.f;

    const int xr = t & 127;
    const int xk = (t >> 7) * 8;
    const int rm = t & 63;
    const int rk = (t >> 6) * 4;

    for (int kc = 0; kc < DHD; kc += 16) {
        float4 x0 = *(const float4*)&X[(size_t)(r0 + xr) * DD + h * DHD + kc + xk];
        float4 x1 = *(const float4*)&X[(size_t)(r0 + xr) * DD + h * DHD + kc + xk + 4];
        #pragma unroll
        for (int i = 0; i < 4; i++) {
            Xs[xk + i][xr]     = ((const float*)&x0)[i] * INV_S4;
            Xs[xk + 4 + i][xr] = ((const float*)&x1)[i] * INV_S4;
        }
        int mg = m0 + rm;
        float4 rv = make_float4(0.f, 0.f, 0.f, 0.f);
        if (mg < MM) rv = *(const float4*)&RF[(size_t)mg * DHD + kc + rk];
        #pragma unroll
        for (int i = 0; i < 4; i++) Rs[rk + i][rm] = ((const float*)&rv)[i];
        __syncthreads();

        #pragma unroll
        for (int k = 0; k < 16; k++) {
            float4 a0 = *(float4*)&Xs[k][ty * 8];
            float4 a1 = *(float4*)&Xs[k][ty * 8 + 4];
            float4 bbv = *(float4*)&Rs[k][tx * 4];
            float a[8] = {a0.x,a0.y,a0.z,a0.w,a1.x,a1.y,a1.z,a1.w};
            float w[4] = {bbv.x,bbv.y,bbv.z,bbv.w};
            #pragma unroll
            for (int i = 0; i < 8; i++)
                #pragma unroll
                for (int j = 0; j < 4; j++) acc[i][j] += a[i] * w[j];
        }
        __syncthreads();
    }

    #pragma unroll
    for (int i = 0; i < 8; i++) {
        int r = r0 + ty * 8 + i;
        float hval = hv[(size_t)r * HH + h];
        int b = r >> 12, l = r & 4095;
        size_t base = (((size_t)(b * HH + h)) * LL + l) * MM;
        #pragma unroll
        for (int j = 0; j < 4; j++) {
            int m = m0 + tx * 4 + j;
            if (m < MM) outp[base + m] = expf(acc[i][j] + hval);
        }
    }
}

// ---------------- phase A (R2 version) ----------------
__global__ void __launch_bounds__(256) phaseA_kernel() {
    __shared__ float sk[8][272];
    __shared__ float sv[8][68];
    const int tx = threadIdx.x & 15;
    const int ty = threadIdx.x >> 4;
    const int c = blockIdx.x, h = blockIdx.y, b = blockIdx.z;
    const int bh = b * HH + h;
    const int l0 = c * CHUNK;
    const float* kb = g_kp + ((size_t)bh * LL + l0) * MM;
    const float* vb = g_V + ((size_t)(b * LL + l0)) * DD + h * DHD;

    float acc[17][4];
    float zacc[17];
    #pragma unroll
    for (int i = 0; i < 17; i++) {
        zacc[i] = 0.f;
        #pragma unroll
        for (int j = 0; j < 4; j++) acc[i][j] = 0.f;
    }

    for (int t0 = 0; t0 < CHUNK; t0 += 8) {
        for (int idx = threadIdx.x; idx < 8 * MM; idx += 256) {
            int t = idx / MM, mm = idx % MM;
            sk[t][mm] = kb[(size_t)(t0 + t) * MM + mm];
        }
        for (int idx = threadIdx.x; idx < 8 * 64; idx += 256) {
            int t = idx >> 6, d = idx & 63;
            sv[t][d] = vb[(size_t)(t0 + t) * DD + d];
        }
        __syncthreads();
        #pragma unroll
        for (int t = 0; t < 8; t++) {
            float4 v4 = *(float4*)&sv[t][tx * 4];
            #pragma unroll
            for (int i = 0; i < 17; i++) {
                float a = sk[t][ty + 16 * i];
                acc[i][0] += a * v4.x; acc[i][1] += a * v4.y;
                acc[i][2] += a * v4.z; acc[i][3] += a * v4.w;
                zacc[i] += a;
            }
        }
        __syncthreads();
    }
    float* Sb = g_S + ((size_t)bh * NCH + c) * (MM * DHD);
    float* zb = g_z + ((size_t)bh * NCH + c) * MM;
    #pragma unroll
    for (int i = 0; i < 17; i++) {
        int m = ty + 16 * i;
        if (m < MM) {
            float4 o = make_float4(acc[i][0], acc[i][1], acc[i][2], acc[i][3]);
            *(float4*)&Sb[(size_t)m * DHD + tx * 4] = o;
            if (tx == 0) zb[m] = zacc[i];
        }
    }
}

// ---------------- exclusive prefix over chunks ----------------
__global__ void scan_kernel(float* data, int per) {
    int gid = blockIdx.x * blockDim.x + threadIdx.x;
    if (gid >= BHT * per) return;
    int bh = gid / per, e = gid % per;
    size_t base = (size_t)bh * NCH * per + e;
    float run = 0.f;
    #pragma unroll 4
    for (int c = 0; c < NCH; c++) {
        size_t idx = base + (size_t)c * per;
        float cur = data[idx];
        data[idx] = run;
        run += cur;
    }
}

// ---------------- phase C (R2 version) ----------------
__global__ void __launch_bounds__(256) phaseC_kernel() {
    __shared__ float A_sh[64 * 65];
    __shared__ float work[64 * 68];
    const int tx = threadIdx.x & 15, ty = threadIdx.x >> 4;
    const int c = blockIdx.x, h = blockIdx.y, b = blockIdx.z;
    const int bh = b * HH + h;
    const int l0 = c * CHUNK;
    const float* qbase = g_qp + ((size_t)bh * LL + l0) * MM;
    const float* kbase = g_kp + ((size_t)bh * LL + l0) * MM;

    float acc[4][4];
    #pragma unroll
    for (int i = 0; i < 4; i++)
        #pragma unroll
        for (int j = 0; j < 4; j++) acc[i][j] = 0.f;

    float* qs = work;
    float* ks = work + 2080;
    for (int m0 = 0; m0 < MM; m0 += 32) {
        for (int idx = threadIdx.x; idx < 64 * 32; idx += 256) {
            int kk = idx & 31, t = idx >> 5;
            int m = m0 + kk;
            float qv = 0.f, kv = 0.f;
            if (m < MM) {
                qv = qbase[(size_t)t * MM + m];
                kv = kbase[(size_t)t * MM + m];
            }
            qs[kk * 65 + t] = qv;
            ks[kk * 65 + t] = kv;
        }
        __syncthreads();
        #pragma unroll 4
        for (int kk = 0; kk < 32; kk++) {
            float a[4], bb2[4];
            #pragma unroll
            for (int i = 0; i < 4; i++) a[i] = qs[kk * 65 + ty * 4 + i];
            #pragma unroll
            for (int j = 0; j < 4; j++) bb2[j] = ks[kk * 65 + tx * 4 + j];
            #pragma unroll
            for (int i = 0; i < 4; i++)
                #pragma unroll
                for (int j = 0; j < 4; j++) acc[i][j] += a[i] * bb2[j];
        }
        __syncthreads();
    }
    #pragma unroll
    for (int i = 0; i < 4; i++) {
        int t = ty * 4 + i;
        #pragma unroll
        for (int j = 0; j < 4; j++) {
            int s = tx * 4 + j;
            A_sh[t * 65 + s] = (s <= t) ? acc[i][j] : 0.f;
        }
    }
    for (int idx = threadIdx.x; idx < 64 * 64; idx += 256) {
        int d = idx & 63, t = idx >> 6;
        work[t * 68 + d] = g_V[((size_t)(b * LL + l0 + t)) * DD + h * DHD + d];
    }
    __syncthreads();

    float num[4][4];
    float den[4];
    #pragma unroll
    for (int i = 0; i < 4; i++) {
        den[i] = 0.f;
        #pragma unroll
        for (int j = 0; j < 4; j++) num[i][j] = 0.f;
    }
    #pragma unroll 4
    for (int j = 0; j < 64; j++) {
        float a[4];
        #pragma unroll
        for (int i = 0; i < 4; i++) a[i] = A_sh[(ty * 4 + i) * 65 + j];
        float4 v = *(float4*)&work[j * 68 + tx * 4];
        #pragma unroll
        for (int i = 0; i < 4; i++) {
            num[i][0] += a[i] * v.x; num[i][1] += a[i] * v.y;
            num[i][2] += a[i] * v.z; num[i][3] += a[i] * v.w;
            den[i] += a[i];
        }
    }
    __syncthreads();

    const float* Sbase = g_S + ((size_t)bh * NCH + c) * (MM * DHD);
    const float* zbase = g_z + ((size_t)bh * NCH + c) * MM;
    float* qs2 = work;
    float* Ss  = work + 2080;
    float* zs  = work + 4256;
    for (int m0 = 0; m0 < MM; m0 += 32) {
        for (int idx = threadIdx.x; idx < 64 * 32; idx += 256) {
            int kk = idx & 31, t = idx >> 5;
            int m = m0 + kk;
            qs2[kk * 65 + t] = (m < MM) ? qbase[(size_t)t * MM + m] : 0.f;
        }
        for (int idx = threadIdx.x; idx < 32 * 64; idx += 256) {
            int d = idx & 63, kk = idx >> 6;
            int m = m0 + kk;
            Ss[kk * 68 + d] = (m < MM) ? Sbase[(size_t)m * DHD + d] : 0.f;
        }
        if (threadIdx.x < 32) {
            int m = m0 + threadIdx.x;
            zs[threadIdx.x] = (m < MM) ? zbase[m] : 0.f;
        }
        __syncthreads();
        #pragma unroll 4
        for (int kk = 0; kk < 32; kk++) {
            float a[4];
            #pragma unroll
            for (int i = 0; i < 4; i++) a[i] = qs2[kk * 65 + ty * 4 + i];
            float4 s4 = *(float4*)&Ss[kk * 68 + tx * 4];
            float zz = zs[kk];
            #pragma unroll
            for (int i = 0; i < 4; i++) {
                num[i][0] += a[i] * s4.x; num[i][1] += a[i] * s4.y;
                num[i][2] += a[i] * s4.z; num[i][3] += a[i] * s4.w;
                den[i] += a[i] * zz;
            }
        }
        __syncthreads();
    }

    #pragma unroll
    for (int i = 0; i < 4; i++) {
        int t = ty * 4 + i;
        float invd = 1.0f / den[i];
        size_t base = ((size_t)(b * LL + l0 + t)) * DD + h * DHD + tx * 4;
        #pragma unroll
        for (int j = 0; j < 4; j++) g_ctx[base + j] = num[i][j] * invd;
    }
}

// ---------------- launch ----------------
extern "C" void kernel_launch(void* const* d_in, const int* in_sizes, int n_in,
                              void* d_out, int out_size) {
    const float* query = (const float*)d_in[0];
    const float* key   = (const float*)d_in[1];
    const float* value = (const float*)d_in[2];
    const float* Wq    = (const float*)d_in[3];
    const float* bq    = (const float*)d_in[4];
    const float* Wk    = (const float*)d_in[5];
    const float* bk    = (const float*)d_in[6];
    const float* Wv    = (const float*)d_in[7];
    const float* bv    = (const float*)d_in[8];
    const float* Wout  = (const float*)d_in[9];
    const float* bout  = (const float*)d_in[10];
    const float* RF    = (const float*)d_in[11];

    float *Qp, *Kp, *Vp, *hqp, *hkp, *qpp, *kpp, *Sp, *zp, *ctxp;
    cudaGetSymbolAddress((void**)&Qp,  g_Q);
    cudaGetSymbolAddress((void**)&Kp,  g_K);
    cudaGetSymbolAddress((void**)&Vp,  g_V);
    cudaGetSymbolAddress((void**)&hqp, g_hq);
    cudaGetSymbolAddress((void**)&hkp, g_hk);
    cudaGetSymbolAddress((void**)&qpp, g_qp);
    cudaGetSymbolAddress((void**)&kpp, g_kp);
    cudaGetSymbolAddress((void**)&Sp,  g_S);
    cudaGetSymbolAddress((void**)&zp,  g_z);
    cudaGetSymbolAddress((void**)&ctxp, g_ctx);

    dim3 gp(DD / 128, NROWS / 128, 3);
    tf32_gemm<<<gp, 256>>>(query, Wq, bq, Qp,
                           key,   Wk, bk, Kp,
                           value, Wv, bv, Vp);

    hq_kernel<<<NROWS, 256>>>(Qp, hqp);
    hq_kernel<<<NROWS, 256>>>(Kp, hkp);

    dim3 fg((MM + 63) / 64, NROWS / 128, HH);
    feat_gemm<<<fg, 256>>>(Qp, RF, hqp, qpp);
    feat_gemm<<<fg, 256>>>(Kp, RF, hkp, kpp);

    dim3 pg(NCH, HH, BB);
    phaseA_kernel<<<pg, 256>>>();

    int perS = MM * DHD;
    scan_kernel<<<(BHT * perS + 255) / 256, 256>>>(Sp, perS);
    scan_kernel<<<(BHT * MM + 255) / 256, 256>>>(zp, MM);

    phaseC_kernel<<<pg, 256>>>();

    dim3 go(DD / 128, NROWS / 128, 1);
    tf32_gemm<<<go, 256>>>(ctxp, Wout, bout, (float*)d_out,
                           ctxp, Wout, bout, (float*)d_out,
                           ctxp, Wout, bout, (float*)d_out);
}

// round 5
// speedup vs baseline: 1.5689x; 1.1070x over previous
#include <cuda_runtime.h>
#include <math.h>
#include <stdint.h>

// ---------------- problem constants ----------------
#define BB    2
#define LL    4096
#define DD    512
#define HH    8
#define DHD   64
#define MM    266
#define NROWS (BB*LL)        // 8192
#define CHUNK 64
#define NCH   (LL/CHUNK)     // 64
#define BHT   (BB*HH)        // 16

#define INV_S4      0.21022410381342863f   // 512^-0.25
#define INV_SQRT512 0.04419417382415922f   // 512^-0.5

// ---------------- scratch ----------------
__device__ float g_Q[NROWS*DD];
__device__ float g_K[NROWS*DD];
__device__ float g_V[NROWS*DD];
__device__ float g_hq[NROWS*HH];
__device__ float g_hk[NROWS*HH];
__device__ float g_qp[(size_t)BHT*LL*MM];
__device__ float g_kp[(size_t)BHT*LL*MM];
__device__ float g_S [(size_t)BHT*NCH*MM*DHD];
__device__ float g_z [(size_t)BHT*NCH*MM];
__device__ float g_ctx[NROWS*DD];

// ---------------- TF32 helpers ----------------
__device__ __forceinline__ uint32_t f2tf(float f) {
    uint32_t u;
    asm("cvt.rna.tf32.f32 %0, %1;" : "=r"(u) : "f"(f));
    return u;
}
__device__ __forceinline__ void mma_tf32(float* c, const uint32_t* a,
                                         uint32_t b0, uint32_t b1) {
    asm volatile(
        "mma.sync.aligned.m16n8k8.row.col.f32.tf32.tf32.f32 "
        "{%0,%1,%2,%3}, {%4,%5,%6,%7}, {%8,%9}, {%0,%1,%2,%3};"
        : "+f"(c[0]), "+f"(c[1]), "+f"(c[2]), "+f"(c[3])
        : "r"(a[0]), "r"(a[1]), "r"(a[2]), "r"(a[3]), "r"(b0), "r"(b1));
}

// ---------------- TF32 GEMM (unchanged from R4) ----------------
__global__ void __launch_bounds__(256, 2)
tf32_gemm(const float* __restrict__ A0, const float* __restrict__ W0,
          const float* __restrict__ bb0, float* __restrict__ C0,
          const float* __restrict__ A1, const float* __restrict__ W1,
          const float* __restrict__ bb1, float* __restrict__ C1,
          const float* __restrict__ A2, const float* __restrict__ W2,
          const float* __restrict__ bb2, float* __restrict__ C2) {
    __shared__ uint32_t As[128][36];
    __shared__ uint32_t Ws[128][36];

    const float* A; const float* W; const float* bias; float* C;
    if (blockIdx.z == 0)      { A = A0; W = W0; bias = bb0; C = C0; }
    else if (blockIdx.z == 1) { A = A1; W = W1; bias = bb1; C = C1; }
    else                      { A = A2; W = W2; bias = bb2; C = C2; }

    const int t = threadIdx.x;
    const int wid = t >> 5, lane = t & 31;
    const int warp_m = (wid & 3) * 32;
    const int warp_n = (wid >> 2) * 64;
    const int row0 = blockIdx.y * 128, col0 = blockIdx.x * 128;
    const int g = lane >> 2, tg = lane & 3;

    float c[2][8][4];
    #pragma unroll
    for (int f = 0; f < 2; f++)
        #pragma unroll
        for (int j = 0; j < 8; j++)
            #pragma unroll
            for (int q = 0; q < 4; q++) c[f][j][q] = 0.f;

    for (int ks = 0; ks < DD; ks += 32) {
        #pragma unroll
        for (int i = 0; i < 4; i++) {
            int idx = t + i * 256;
            int r = idx >> 3, q = idx & 7;
            float4 av = *(const float4*)&A[(size_t)(row0 + r) * DD + ks + q * 4];
            float4 wv = *(const float4*)&W[(size_t)(col0 + r) * DD + ks + q * 4];
            uint4 au = make_uint4(f2tf(av.x), f2tf(av.y), f2tf(av.z), f2tf(av.w));
            uint4 wu = make_uint4(f2tf(wv.x), f2tf(wv.y), f2tf(wv.z), f2tf(wv.w));
            *(uint4*)&As[r][q * 4] = au;
            *(uint4*)&Ws[r][q * 4] = wu;
        }
        __syncthreads();
        #pragma unroll
        for (int k8 = 0; k8 < 32; k8 += 8) {
            uint32_t a[2][4];
            #pragma unroll
            for (int f = 0; f < 2; f++) {
                int m0 = warp_m + 16 * f;
                a[f][0] = As[m0 + g][k8 + tg];
                a[f][1] = As[m0 + g + 8][k8 + tg];
                a[f][2] = As[m0 + g][k8 + tg + 4];
                a[f][3] = As[m0 + g + 8][k8 + tg + 4];
            }
            #pragma unroll
            for (int j = 0; j < 8; j++) {
                uint32_t b0 = Ws[warp_n + 8 * j + g][k8 + tg];
                uint32_t b1 = Ws[warp_n + 8 * j + g][k8 + tg + 4];
                mma_tf32(c[0][j], a[0], b0, b1);
                mma_tf32(c[1][j], a[1], b0, b1);
            }
        }
        __syncthreads();
    }

    #pragma unroll
    for (int f = 0; f < 2; f++) {
        int r0 = row0 + warp_m + 16 * f + g;
        #pragma unroll
        for (int j = 0; j < 8; j++) {
            int cidx = col0 + warp_n + 8 * j + 2 * tg;
            float bx = bias[cidx], by = bias[cidx + 1];
            float2 o0 = make_float2(c[f][j][0] + bx, c[f][j][1] + by);
            float2 o1 = make_float2(c[f][j][2] + bx, c[f][j][3] + by);
            *(float2*)&C[(size_t)r0 * DD + cidx] = o0;
            *(float2*)&C[(size_t)(r0 + 8) * DD + cidx] = o1;
        }
    }
}

// ---------------- per-(row,head) -0.5*||x/scale||^2 ----------------
__global__ void hq_kernel(const float* __restrict__ X, float* __restrict__ hout) {
    int row = blockIdx.x;
    int w = threadIdx.x >> 5, lane = threadIdx.x & 31;
    const float* xr = X + (size_t)row * DD + w * DHD;
    float2 v = *(const float2*)&xr[lane * 2];
    float s = v.x * v.x + v.y * v.y;
    #pragma unroll
    for (int off = 16; off; off >>= 1) s += __shfl_xor_sync(0xffffffffu, s, off);
    if (lane == 0) hout[(size_t)row * HH + w] = -0.5f * INV_SQRT512 * s;
}

// ---------------- feature map (unchanged) ----------------
__global__ void __launch_bounds__(256) feat_gemm(const float* __restrict__ X,
                                                 const float* __restrict__ RF,
                                                 const float* __restrict__ hv,
                                                 float* __restrict__ outp) {
    __shared__ float Xs[16][132];
    __shared__ float Rs[16][68];
    const int t = threadIdx.x;
    const int h  = blockIdx.z;
    const int r0 = blockIdx.y * 128;
    const int m0 = blockIdx.x * 64;
    const int ty = t >> 4, tx = t & 15;

    float acc[8][4];
    #pragma unroll
    for (int i = 0; i < 8; i++)
        #pragma unroll
        for (int j = 0; j < 4; j++) acc[i][j] = 0.f;

    const int xr = t & 127;
    const int xk = (t >> 7) * 8;
    const int rm = t & 63;
    const int rk = (t >> 6) * 4;

    for (int kc = 0; kc < DHD; kc += 16) {
        float4 x0 = *(const float4*)&X[(size_t)(r0 + xr) * DD + h * DHD + kc + xk];
        float4 x1 = *(const float4*)&X[(size_t)(r0 + xr) * DD + h * DHD + kc + xk + 4];
        #pragma unroll
        for (int i = 0; i < 4; i++) {
            Xs[xk + i][xr]     = ((const float*)&x0)[i] * INV_S4;
            Xs[xk + 4 + i][xr] = ((const float*)&x1)[i] * INV_S4;
        }
        int mg = m0 + rm;
        float4 rv = make_float4(0.f, 0.f, 0.f, 0.f);
        if (mg < MM) rv = *(const float4*)&RF[(size_t)mg * DHD + kc + rk];
        #pragma unroll
        for (int i = 0; i < 4; i++) Rs[rk + i][rm] = ((const float*)&rv)[i];
        __syncthreads();

        #pragma unroll
        for (int k = 0; k < 16; k++) {
            float4 a0 = *(float4*)&Xs[k][ty * 8];
            float4 a1 = *(float4*)&Xs[k][ty * 8 + 4];
            float4 bbv = *(float4*)&Rs[k][tx * 4];
            float a[8] = {a0.x,a0.y,a0.z,a0.w,a1.x,a1.y,a1.z,a1.w};
            float w[4] = {bbv.x,bbv.y,bbv.z,bbv.w};
            #pragma unroll
            for (int i = 0; i < 8; i++)
                #pragma unroll
                for (int j = 0; j < 4; j++) acc[i][j] += a[i] * w[j];
        }
        __syncthreads();
    }

    #pragma unroll
    for (int i = 0; i < 8; i++) {
        int r = r0 + ty * 8 + i;
        float hval = hv[(size_t)r * HH + h];
        int b = r >> 12, l = r & 4095;
        size_t base = (((size_t)(b * HH + h)) * LL + l) * MM;
        #pragma unroll
        for (int j = 0; j < 4; j++) {
            int m = m0 + tx * 4 + j;
            if (m < MM) outp[base + m] = expf(acc[i][j] + hval);
        }
    }
}

// ---------------- phase A (TF32 mma): S_c[m][d] = sum_t k'[t][m] v[t][d]; z fused ----------------
// grid (NCH, BHT), 256 threads = 8 warps. 17 m-tiles of 16 (warp w: tiles {w, w+8}, warp0 also 16).
__global__ void __launch_bounds__(256) phaseA_kernel() {
    __shared__ uint32_t sk[16][276];   // k' t-chunk, tf32, [t][m]
    __shared__ uint32_t sv[16][68];    // v  t-chunk, tf32, [t][d]

    const int tid = threadIdx.x;
    const int wid = tid >> 5, lane = tid & 31;
    const int g = lane >> 2, tg = lane & 3;
    const int c = blockIdx.x, bh = blockIdx.y;
    const int b = bh >> 3, h = bh & 7;
    const int l0 = c * CHUNK;
    const float* kb = g_kp + ((size_t)bh * LL + l0) * MM;
    const float* vb = g_V + ((size_t)(b * LL + l0)) * DD + h * DHD;

    const int nt = (wid == 0) ? 3 : 2;
    int tile0 = wid, tile1 = wid + 8, tile2 = 16;

    float acc[3][8][4];
    #pragma unroll
    for (int ti = 0; ti < 3; ti++)
        #pragma unroll
        for (int j = 0; j < 8; j++)
            #pragma unroll
            for (int q = 0; q < 4; q++) acc[ti][j][q] = 0.f;
    float zacc0 = 0.f, zacc1 = 0.f;

    const int svt = tid >> 4, svd = (tid & 15) * 4;

    for (int t0 = 0; t0 < CHUNK; t0 += 16) {
        // stage k' [16 t][272 m] via float2 (MM=266: 8B aligned rows)
        #pragma unroll 3
        for (int idx = tid; idx < 16 * 136; idx += 256) {
            int t = idx / 136, m2 = (idx % 136) * 2;
            float2 kv = make_float2(0.f, 0.f);
            if (m2 < MM) kv = *(const float2*)&kb[(size_t)(t0 + t) * MM + m2];
            sk[t][m2]     = f2tf(kv.x);
            sk[t][m2 + 1] = f2tf(kv.y);
        }
        // stage v [16 t][64 d]
        {
            float4 vv = *(const float4*)&vb[(size_t)(t0 + svt) * DD + svd];
            sv[svt][svd]     = f2tf(vv.x);
            sv[svt][svd + 1] = f2tf(vv.y);
            sv[svt][svd + 2] = f2tf(vv.z);
            sv[svt][svd + 3] = f2tf(vv.w);
        }
        __syncthreads();
        // z partials (m = tid, and m = 256+tid for tid<16)
        #pragma unroll
        for (int t = 0; t < 16; t++) zacc0 += __uint_as_float(sk[t][tid]);
        if (tid < 16) {
            #pragma unroll
            for (int t = 0; t < 16; t++) zacc1 += __uint_as_float(sk[t][256 + tid]);
        }
        // mma: A[m][k=t] = sk[k][m], B[k=t][n=d] = sv[k][n]
        #pragma unroll
        for (int k8 = 0; k8 < 16; k8 += 8) {
            uint32_t bf[8][2];
            #pragma unroll
            for (int j = 0; j < 8; j++) {
                bf[j][0] = sv[k8 + tg][j * 8 + g];
                bf[j][1] = sv[k8 + tg + 4][j * 8 + g];
            }
            #pragma unroll
            for (int ti = 0; ti < 3; ti++) {
                if (ti >= nt) break;
                int m0 = (ti == 0 ? tile0 : (ti == 1 ? tile1 : tile2)) * 16;
                uint32_t a[4];
                a[0] = sk[k8 + tg][m0 + g];
                a[1] = sk[k8 + tg][m0 + g + 8];
                a[2] = sk[k8 + tg + 4][m0 + g];
                a[3] = sk[k8 + tg + 4][m0 + g + 8];
                #pragma unroll
                for (int j = 0; j < 8; j++) mma_tf32(acc[ti][j], a, bf[j][0], bf[j][1]);
            }
        }
        __syncthreads();
    }

    // store S (guard m < MM) and z
    float* Sb = g_S + ((size_t)bh * NCH + c) * (MM * DHD);
    #pragma unroll
    for (int ti = 0; ti < 3; ti++) {
        if (ti >= nt) break;
        int m0 = (ti == 0 ? tile0 : (ti == 1 ? tile1 : tile2)) * 16;
        int mlo = m0 + g, mhi = m0 + g + 8;
        #pragma unroll
        for (int j = 0; j < 8; j++) {
            int d = j * 8 + 2 * tg;
            if (mlo < MM) *(float2*)&Sb[(size_t)mlo * DHD + d] =
                make_float2(acc[ti][j][0], acc[ti][j][1]);
            if (mhi < MM) *(float2*)&Sb[(size_t)mhi * DHD + d] =
                make_float2(acc[ti][j][2], acc[ti][j][3]);
        }
    }
    float* zb = g_z + ((size_t)bh * NCH + c) * MM;
    zb[tid] = zacc0;                       // m = 0..255 (< 266)
    if (tid < MM - 256) zb[256 + tid] = zacc1;   // m = 256..265
}

// ---------------- exclusive prefix over chunks ----------------
__global__ void scan_kernel(float* data, int per) {
    int gid = blockIdx.x * blockDim.x + threadIdx.x;
    if (gid >= BHT * per) return;
    int bh = gid / per, e = gid % per;
    size_t base = (size_t)bh * NCH * per + e;
    float run = 0.f;
    #pragma unroll 4
    for (int c = 0; c < NCH; c++) {
        size_t idx = base + (size_t)c * per;
        float cur = data[idx];
        data[idx] = run;
        run += cur;
    }
}

// ---------------- phase C (TF32 mma): scores + mask + A*V + Q'*S_prefix + divide ----------------
// grid (NCH, BHT), 256 threads = 8 warps; warp tile 16x32 over 64x64 outputs.
__global__ void __launch_bounds__(256) phaseC_kernel() {
    __shared__ uint32_t A_sh[64][68];      // masked scores (tf32)
    __shared__ uint32_t wbuf[4608];        // qs[64][36]+ks[64][36] | Vs[64][68] | qs[64][36]+Ss[32][68]
    __shared__ float zs[32];
    __shared__ float dred[4][64];
    __shared__ float den_sh[64];

    uint32_t (*qs)[36] = (uint32_t(*)[36])wbuf;
    uint32_t (*ks)[36] = (uint32_t(*)[36])(wbuf + 2304);
    uint32_t (*Vs)[68] = (uint32_t(*)[68])wbuf;
    uint32_t (*Ss)[68] = (uint32_t(*)[68])(wbuf + 2304);

    const int tid = threadIdx.x;
    const int wid = tid >> 5, lane = tid & 31;
    const int g = lane >> 2, tg = lane & 3;
    const int t0 = (wid & 3) * 16;
    const int n0 = (wid >> 2) * 32;
    const int c = blockIdx.x, bh = blockIdx.y;
    const int b = bh >> 3, h = bh & 7;
    const int l0 = c * CHUNK;
    const float* qb = g_qp + ((size_t)bh * LL + l0) * MM;
    const float* kb = g_kp + ((size_t)bh * LL + l0) * MM;
    const float* zb = g_z + ((size_t)bh * NCH + c) * MM;
    const float* Sb = g_S + ((size_t)bh * NCH + c) * (MM * DHD);

    // ---- gemm1: scores = Q'K'^T over m (K dim), plus den_q = Q'.z (SIMT) ----
    float c1[4][4];
    #pragma unroll
    for (int j = 0; j < 4; j++)
        #pragma unroll
        for (int q = 0; q < 4; q++) c1[j][q] = 0.f;
    float dq = 0.f;
    const int dt = tid & 63, dslice = tid >> 6;

    for (int m0 = 0; m0 < 272; m0 += 32) {
        #pragma unroll 4
        for (int idx = tid; idx < 64 * 16; idx += 256) {
            int t = idx >> 4, m2 = (idx & 15) * 2;
            int m = m0 + m2;
            float2 qv = make_float2(0.f, 0.f), kv = make_float2(0.f, 0.f);
            if (m < MM) {
                qv = *(const float2*)&qb[(size_t)t * MM + m];
                kv = *(const float2*)&kb[(size_t)t * MM + m];
            }
            qs[t][m2] = f2tf(qv.x); qs[t][m2 + 1] = f2tf(qv.y);
            ks[t][m2] = f2tf(kv.x); ks[t][m2 + 1] = f2tf(kv.y);
        }
        if (tid < 32) zs[tid] = (m0 + tid < MM) ? zb[m0 + tid] : 0.f;
        __syncthreads();
        #pragma unroll
        for (int i = 0; i < 8; i++) {
            int mm = dslice * 8 + i;
            dq += __uint_as_float(qs[dt][mm]) * zs[mm];
        }
        #pragma unroll
        for (int k8 = 0; k8 < 32; k8 += 8) {
            uint32_t a[4];
            a[0] = qs[t0 + g][k8 + tg];
            a[1] = qs[t0 + g + 8][k8 + tg];
            a[2] = qs[t0 + g][k8 + tg + 4];
            a[3] = qs[t0 + g + 8][k8 + tg + 4];
            #pragma unroll
            for (int j = 0; j < 4; j++) {
                uint32_t b0 = ks[n0 + j * 8 + g][k8 + tg];
                uint32_t b1 = ks[n0 + j * 8 + g][k8 + tg + 4];
                mma_tf32(c1[j], a, b0, b1);
            }
        }
        __syncthreads();
    }
    dred[dslice][dt] = dq;

    // ---- causal mask -> A_sh (tf32) ----
    {
        int ta = t0 + g, tb2 = t0 + g + 8;
        #pragma unroll
        for (int j = 0; j < 4; j++) {
            int s = n0 + j * 8 + 2 * tg;
            A_sh[ta][s]      = f2tf((s     <= ta)  ? c1[j][0] : 0.f);
            A_sh[ta][s + 1]  = f2tf((s + 1 <= ta)  ? c1[j][1] : 0.f);
            A_sh[tb2][s]     = f2tf((s     <= tb2) ? c1[j][2] : 0.f);
            A_sh[tb2][s + 1] = f2tf((s + 1 <= tb2) ? c1[j][3] : 0.f);
        }
    }
    __syncthreads();

    // den = rowsum(masked A) + dq
    if (tid < 64) {
        float r = dred[0][tid] + dred[1][tid] + dred[2][tid] + dred[3][tid];
        #pragma unroll 8
        for (int s = 0; s < 64; s++) r += __uint_as_float(A_sh[tid][s]);
        den_sh[tid] = r;
    }

    // ---- stage V; pass2a: num = A_masked * V (K=64) ----
    {
        int t = tid >> 2, d16 = (tid & 3) * 16;
        const float* vr = &g_V[((size_t)(b * LL + l0 + t)) * DD + h * DHD + d16];
        #pragma unroll
        for (int q = 0; q < 4; q++) {
            float4 vv = *(const float4*)&vr[q * 4];
            Vs[t][d16 + q * 4]     = f2tf(vv.x);
            Vs[t][d16 + q * 4 + 1] = f2tf(vv.y);
            Vs[t][d16 + q * 4 + 2] = f2tf(vv.z);
            Vs[t][d16 + q * 4 + 3] = f2tf(vv.w);
        }
    }
    __syncthreads();

    float c2[4][4];
    #pragma unroll
    for (int j = 0; j < 4; j++)
        #pragma unroll
        for (int q = 0; q < 4; q++) c2[j][q] = 0.f;

    #pragma unroll
    for (int k8 = 0; k8 < 64; k8 += 8) {
        uint32_t a[4];
        a[0] = A_sh[t0 + g][k8 + tg];
        a[1] = A_sh[t0 + g + 8][k8 + tg];
        a[2] = A_sh[t0 + g][k8 + tg + 4];
        a[3] = A_sh[t0 + g + 8][k8 + tg + 4];
        #pragma unroll
        for (int j = 0; j < 4; j++) {
            uint32_t b0 = Vs[k8 + tg][n0 + j * 8 + g];
            uint32_t b1 = Vs[k8 + tg + 4][n0 + j * 8 + g];
            mma_tf32(c2[j], a, b0, b1);
        }
    }
    __syncthreads();

    // ---- pass2b: num += Q' * S_prefix (K=266) ----
    for (int m0 = 0; m0 < 272; m0 += 32) {
        #pragma unroll 4
        for (int idx = tid; idx < 64 * 16; idx += 256) {
            int t = idx >> 4, m2 = (idx & 15) * 2;
            int m = m0 + m2;
            float2 qv = make_float2(0.f, 0.f);
            if (m < MM) qv = *(const float2*)&qb[(size_t)t * MM + m];
            qs[t][m2] = f2tf(qv.x); qs[t][m2 + 1] = f2tf(qv.y);
        }
        #pragma unroll 2
        for (int idx = tid; idx < 32 * 16; idx += 256) {
            int mm = idx >> 4, d4 = (idx & 15) * 4;
            int m = m0 + mm;
            float4 sv4 = make_float4(0.f, 0.f, 0.f, 0.f);
            if (m < MM) sv4 = *(const float4*)&Sb[(size_t)m * DHD + d4];
            Ss[mm][d4]     = f2tf(sv4.x);
            Ss[mm][d4 + 1] = f2tf(sv4.y);
            Ss[mm][d4 + 2] = f2tf(sv4.z);
            Ss[mm][d4 + 3] = f2tf(sv4.w);
        }
        __syncthreads();
        #pragma unroll
        for (int k8 = 0; k8 < 32; k8 += 8) {
            uint32_t a[4];
            a[0] = qs[t0 + g][k8 + tg];
            a[1] = qs[t0 + g + 8][k8 + tg];
            a[2] = qs[t0 + g][k8 + tg + 4];
            a[3] = qs[t0 + g + 8][k8 + tg + 4];
            #pragma unroll
            for (int j = 0; j < 4; j++) {
                uint32_t b0 = Ss[k8 + tg][n0 + j * 8 + g];
                uint32_t b1 = Ss[k8 + tg + 4][n0 + j * 8 + g];
                mma_tf32(c2[j], a, b0, b1);
            }
        }
        __syncthreads();
    }

    // ---- epilogue: ctx = num / den ----
    {
        int ta = t0 + g, tb2 = t0 + g + 8;
        float inva = 1.0f / den_sh[ta];
        float invb = 1.0f / den_sh[tb2];
        #pragma unroll
        for (int j = 0; j < 4; j++) {
            int d = n0 + j * 8 + 2 * tg;
            *(float2*)&g_ctx[((size_t)(b * LL + l0 + ta)) * DD + h * DHD + d] =
                make_float2(c2[j][0] * inva, c2[j][1] * inva);
            *(float2*)&g_ctx[((size_t)(b * LL + l0 + tb2)) * DD + h * DHD + d] =
                make_float2(c2[j][2] * invb, c2[j][3] * invb);
        }
    }
}

// ---------------- launch ----------------
extern "C" void kernel_launch(void* const* d_in, const int* in_sizes, int n_in,
                              void* d_out, int out_size) {
    const float* query = (const float*)d_in[0];
    const float* key   = (const float*)d_in[1];
    const float* value = (const float*)d_in[2];
    const float* Wq    = (const float*)d_in[3];
    const float* bq    = (const float*)d_in[4];
    const float* Wk    = (const float*)d_in[5];
    const float* bk    = (const float*)d_in[6];
    const float* Wv    = (const float*)d_in[7];
    const float* bv    = (const float*)d_in[8];
    const float* Wout  = (const float*)d_in[9];
    const float* bout  = (const float*)d_in[10];
    const float* RF    = (const float*)d_in[11];

    float *Qp, *Kp, *Vp, *hqp, *hkp, *qpp, *kpp, *Sp, *zp, *ctxp;
    cudaGetSymbolAddress((void**)&Qp,  g_Q);
    cudaGetSymbolAddress((void**)&Kp,  g_K);
    cudaGetSymbolAddress((void**)&Vp,  g_V);
    cudaGetSymbolAddress((void**)&hqp, g_hq);
    cudaGetSymbolAddress((void**)&hkp, g_hk);
    cudaGetSymbolAddress((void**)&qpp, g_qp);
    cudaGetSymbolAddress((void**)&kpp, g_kp);
    cudaGetSymbolAddress((void**)&Sp,  g_S);
    cudaGetSymbolAddress((void**)&zp,  g_z);
    cudaGetSymbolAddress((void**)&ctxp, g_ctx);

    dim3 gp(DD / 128, NROWS / 128, 3);
    tf32_gemm<<<gp, 256>>>(query, Wq, bq, Qp,
                           key,   Wk, bk, Kp,
                           value, Wv, bv, Vp);

    hq_kernel<<<NROWS, 256>>>(Qp, hqp);
    hq_kernel<<<NROWS, 256>>>(Kp, hkp);

    dim3 fg((MM + 63) / 64, NROWS / 128, HH);
    feat_gemm<<<fg, 256>>>(Qp, RF, hqp, qpp);
    feat_gemm<<<fg, 256>>>(Kp, RF, hkp, kpp);

    dim3 pg(NCH, BHT);
    phaseA_kernel<<<pg, 256>>>();

    int perS = MM * DHD;
    scan_kernel<<<(BHT * perS + 255) / 256, 256>>>(Sp, perS);
    scan_kernel<<<(BHT * MM + 255) / 256, 256>>>(zp, MM);

    phaseC_kernel<<<pg, 256>>>();

    dim3 go(DD / 128, NROWS / 128, 1);
    tf32_gemm<<<go, 256>>>(ctxp, Wout, bout, (float*)d_out,
                           ctxp, Wout, bout, (float*)d_out,
                           ctxp, Wout, bout, (float*)d_out);
}

// round 6
// speedup vs baseline: 1.7319x; 1.1039x over previous
#include <cuda_runtime.h>
#include <math.h>
#include <stdint.h>

// ---------------- problem constants ----------------
#define BB    2
#define LL    4096
#define DD    512
#define HH    8
#define DHD   64
#define MM    266
#define NROWS (BB*LL)        // 8192
#define CHUNK 64
#define NCH   (LL/CHUNK)     // 64
#define BHT   (BB*HH)        // 16

#define INV_S4      0.21022410381342863f   // 512^-0.25
#define INV_SQRT512 0.04419417382415922f   // 512^-0.5

// ---------------- scratch ----------------
__device__ float g_Q[NROWS*DD];
__device__ float g_K[NROWS*DD];
__device__ float g_V[NROWS*DD];
__device__ float g_hq[NROWS*HH];
__device__ float g_hk[NROWS*HH];
__device__ float g_qp[(size_t)BHT*LL*MM];
__device__ float g_kp[(size_t)BHT*LL*MM];
__device__ float g_S [(size_t)BHT*NCH*MM*DHD];
__device__ float g_z [(size_t)BHT*NCH*MM];
__device__ float g_ctx[NROWS*DD];

// ---------------- TF32 helpers ----------------
__device__ __forceinline__ uint32_t f2tf(float f) {
    uint32_t u;
    asm("cvt.rna.tf32.f32 %0, %1;" : "=r"(u) : "f"(f));
    return u;
}
__device__ __forceinline__ void mma_tf32(float* c, const uint32_t* a,
                                         uint32_t b0, uint32_t b1) {
    asm volatile(
        "mma.sync.aligned.m16n8k8.row.col.f32.tf32.tf32.f32 "
        "{%0,%1,%2,%3}, {%4,%5,%6,%7}, {%8,%9}, {%0,%1,%2,%3};"
        : "+f"(c[0]), "+f"(c[1]), "+f"(c[2]), "+f"(c[3])
        : "r"(a[0]), "r"(a[1]), "r"(a[2]), "r"(a[3]), "r"(b0), "r"(b1));
}

// ---------------- TF32 GEMM (projections / output) ----------------
__global__ void __launch_bounds__(256, 2)
tf32_gemm(const float* __restrict__ A0, const float* __restrict__ W0,
          const float* __restrict__ bb0, float* __restrict__ C0,
          const float* __restrict__ A1, const float* __restrict__ W1,
          const float* __restrict__ bb1, float* __restrict__ C1,
          const float* __restrict__ A2, const float* __restrict__ W2,
          const float* __restrict__ bb2, float* __restrict__ C2) {
    __shared__ uint32_t As[128][36];
    __shared__ uint32_t Ws[128][36];

    const float* A; const float* W; const float* bias; float* C;
    if (blockIdx.z == 0)      { A = A0; W = W0; bias = bb0; C = C0; }
    else if (blockIdx.z == 1) { A = A1; W = W1; bias = bb1; C = C1; }
    else                      { A = A2; W = W2; bias = bb2; C = C2; }

    const int t = threadIdx.x;
    const int wid = t >> 5, lane = t & 31;
    const int warp_m = (wid & 3) * 32;
    const int warp_n = (wid >> 2) * 64;
    const int row0 = blockIdx.y * 128, col0 = blockIdx.x * 128;
    const int g = lane >> 2, tg = lane & 3;

    float c[2][8][4];
    #pragma unroll
    for (int f = 0; f < 2; f++)
        #pragma unroll
        for (int j = 0; j < 8; j++)
            #pragma unroll
            for (int q = 0; q < 4; q++) c[f][j][q] = 0.f;

    for (int ks = 0; ks < DD; ks += 32) {
        #pragma unroll
        for (int i = 0; i < 4; i++) {
            int idx = t + i * 256;
            int r = idx >> 3, q = idx & 7;
            float4 av = *(const float4*)&A[(size_t)(row0 + r) * DD + ks + q * 4];
            float4 wv = *(const float4*)&W[(size_t)(col0 + r) * DD + ks + q * 4];
            uint4 au = make_uint4(f2tf(av.x), f2tf(av.y), f2tf(av.z), f2tf(av.w));
            uint4 wu = make_uint4(f2tf(wv.x), f2tf(wv.y), f2tf(wv.z), f2tf(wv.w));
            *(uint4*)&As[r][q * 4] = au;
            *(uint4*)&Ws[r][q * 4] = wu;
        }
        __syncthreads();
        #pragma unroll
        for (int k8 = 0; k8 < 32; k8 += 8) {
            uint32_t a[2][4];
            #pragma unroll
            for (int f = 0; f < 2; f++) {
                int m0 = warp_m + 16 * f;
                a[f][0] = As[m0 + g][k8 + tg];
                a[f][1] = As[m0 + g + 8][k8 + tg];
                a[f][2] = As[m0 + g][k8 + tg + 4];
                a[f][3] = As[m0 + g + 8][k8 + tg + 4];
            }
            #pragma unroll
            for (int j = 0; j < 8; j++) {
                uint32_t b0 = Ws[warp_n + 8 * j + g][k8 + tg];
                uint32_t b1 = Ws[warp_n + 8 * j + g][k8 + tg + 4];
                mma_tf32(c[0][j], a[0], b0, b1);
                mma_tf32(c[1][j], a[1], b0, b1);
            }
        }
        __syncthreads();
    }

    #pragma unroll
    for (int f = 0; f < 2; f++) {
        int r0 = row0 + warp_m + 16 * f + g;
        #pragma unroll
        for (int j = 0; j < 8; j++) {
            int cidx = col0 + warp_n + 8 * j + 2 * tg;
            float bx = bias[cidx], by = bias[cidx + 1];
            float2 o0 = make_float2(c[f][j][0] + bx, c[f][j][1] + by);
            float2 o1 = make_float2(c[f][j][2] + bx, c[f][j][3] + by);
            *(float2*)&C[(size_t)r0 * DD + cidx] = o0;
            *(float2*)&C[(size_t)(r0 + 8) * DD + cidx] = o1;
        }
    }
}

// ---------------- per-(row,head) -0.5*||x/scale||^2 ----------------
__global__ void hq_kernel(const float* __restrict__ X, float* __restrict__ hout) {
    int row = blockIdx.x;
    int w = threadIdx.x >> 5, lane = threadIdx.x & 31;
    const float* xr = X + (size_t)row * DD + w * DHD;
    float2 v = *(const float2*)&xr[lane * 2];
    float s = v.x * v.x + v.y * v.y;
    #pragma unroll
    for (int off = 16; off; off >>= 1) s += __shfl_xor_sync(0xffffffffu, s, off);
    if (lane == 0) hout[(size_t)row * HH + w] = -0.5f * INV_SQRT512 * s;
}

// ---------------- feature map (TF32 mma): out = exp(hq + (x/s)·RF^T) ----------------
// grid (5 m-tiles of 64, 64 row-tiles of 128, 8 heads), 256 threads = 8 warps (4x2).
__global__ void __launch_bounds__(256) feat_gemm(const float* __restrict__ X,
                                                 const float* __restrict__ RF,
                                                 const float* __restrict__ hv,
                                                 float* __restrict__ outp) {
    __shared__ uint32_t Xs[128][36];
    __shared__ uint32_t Rs[64][36];

    const int t = threadIdx.x;
    const int wid = t >> 5, lane = t & 31;
    const int g = lane >> 2, tg = lane & 3;
    const int warp_m = (wid & 3) * 32;    // rows
    const int warp_n = (wid >> 2) * 32;   // m cols
    const int h  = blockIdx.z;
    const int r0 = blockIdx.y * 128;
    const int m0 = blockIdx.x * 64;

    float c[2][4][4];
    #pragma unroll
    for (int f = 0; f < 2; f++)
        #pragma unroll
        for (int j = 0; j < 4; j++)
            #pragma unroll
            for (int q = 0; q < 4; q++) c[f][j][q] = 0.f;

    for (int kc = 0; kc < DHD; kc += 32) {
        // stage X (scaled, tf32): 128 rows x 32 k
        #pragma unroll
        for (int i = 0; i < 4; i++) {
            int idx = t + i * 256;
            int r = idx >> 3, q = idx & 7;
            float4 xv = *(const float4*)&X[(size_t)(r0 + r) * DD + h * DHD + kc + q * 4];
            uint4 xu = make_uint4(f2tf(xv.x * INV_S4), f2tf(xv.y * INV_S4),
                                  f2tf(xv.z * INV_S4), f2tf(xv.w * INV_S4));
            *(uint4*)&Xs[r][q * 4] = xu;
        }
        // stage RF (tf32): 64 m x 32 k, guarded
        #pragma unroll
        for (int i = 0; i < 2; i++) {
            int idx = t + i * 256;
            int mr = idx >> 3, q = idx & 7;
            float4 rv = make_float4(0.f, 0.f, 0.f, 0.f);
            if (m0 + mr < MM) rv = *(const float4*)&RF[(size_t)(m0 + mr) * DHD + kc + q * 4];
            uint4 ru = make_uint4(f2tf(rv.x), f2tf(rv.y), f2tf(rv.z), f2tf(rv.w));
            *(uint4*)&Rs[mr][q * 4] = ru;
        }
        __syncthreads();
        #pragma unroll
        for (int k8 = 0; k8 < 32; k8 += 8) {
            uint32_t a[2][4];
            #pragma unroll
            for (int f = 0; f < 2; f++) {
                int mw = warp_m + 16 * f;
                a[f][0] = Xs[mw + g][k8 + tg];
                a[f][1] = Xs[mw + g + 8][k8 + tg];
                a[f][2] = Xs[mw + g][k8 + tg + 4];
                a[f][3] = Xs[mw + g + 8][k8 + tg + 4];
            }
            #pragma unroll
            for (int j = 0; j < 4; j++) {
                uint32_t b0 = Rs[warp_n + 8 * j + g][k8 + tg];
                uint32_t b1 = Rs[warp_n + 8 * j + g][k8 + tg + 4];
                mma_tf32(c[0][j], a[0], b0, b1);
                mma_tf32(c[1][j], a[1], b0, b1);
            }
        }
        __syncthreads();
    }

    // epilogue: exp(acc + h), write guarded
    #pragma unroll
    for (int f = 0; f < 2; f++) {
        int ra = r0 + warp_m + 16 * f + g;      // row for c[f][j][0..1]
        int rb = ra + 8;                        // row for c[f][j][2..3]
        float ha = hv[(size_t)ra * HH + h];
        float hb = hv[(size_t)rb * HH + h];
        int ba = ra >> 12, la = ra & 4095;
        int bb = rb >> 12, lb = rb & 4095;
        size_t basea = (((size_t)(ba * HH + h)) * LL + la) * MM;
        size_t baseb = (((size_t)(bb * HH + h)) * LL + lb) * MM;
        #pragma unroll
        for (int j = 0; j < 4; j++) {
            int m = m0 + warp_n + 8 * j + 2 * tg;
            if (m < MM)     outp[basea + m]     = __expf(c[f][j][0] + ha);
            if (m + 1 < MM) outp[basea + m + 1] = __expf(c[f][j][1] + ha);
            if (m < MM)     outp[baseb + m]     = __expf(c[f][j][2] + hb);
            if (m + 1 < MM) outp[baseb + m + 1] = __expf(c[f][j][3] + hb);
        }
    }
}

// ---------------- phase A (TF32 mma) ----------------
__global__ void __launch_bounds__(256) phaseA_kernel() {
    __shared__ uint32_t sk[16][276];
    __shared__ uint32_t sv[16][68];

    const int tid = threadIdx.x;
    const int wid = tid >> 5, lane = tid & 31;
    const int g = lane >> 2, tg = lane & 3;
    const int c = blockIdx.x, bh = blockIdx.y;
    const int b = bh >> 3, h = bh & 7;
    const int l0 = c * CHUNK;
    const float* kb = g_kp + ((size_t)bh * LL + l0) * MM;
    const float* vb = g_V + ((size_t)(b * LL + l0)) * DD + h * DHD;

    const int nt = (wid == 0) ? 3 : 2;
    int tile0 = wid, tile1 = wid + 8, tile2 = 16;

    float acc[3][8][4];
    #pragma unroll
    for (int ti = 0; ti < 3; ti++)
        #pragma unroll
        for (int j = 0; j < 8; j++)
            #pragma unroll
            for (int q = 0; q < 4; q++) acc[ti][j][q] = 0.f;
    float zacc0 = 0.f, zacc1 = 0.f;

    const int svt = tid >> 4, svd = (tid & 15) * 4;

    for (int t0 = 0; t0 < CHUNK; t0 += 16) {
        #pragma unroll 3
        for (int idx = tid; idx < 16 * 136; idx += 256) {
            int t = idx / 136, m2 = (idx % 136) * 2;
            float2 kv = make_float2(0.f, 0.f);
            if (m2 < MM) kv = *(const float2*)&kb[(size_t)(t0 + t) * MM + m2];
            sk[t][m2]     = f2tf(kv.x);
            sk[t][m2 + 1] = f2tf(kv.y);
        }
        {
            float4 vv = *(const float4*)&vb[(size_t)(t0 + svt) * DD + svd];
            sv[svt][svd]     = f2tf(vv.x);
            sv[svt][svd + 1] = f2tf(vv.y);
            sv[svt][svd + 2] = f2tf(vv.z);
            sv[svt][svd + 3] = f2tf(vv.w);
        }
        __syncthreads();
        #pragma unroll
        for (int t = 0; t < 16; t++) zacc0 += __uint_as_float(sk[t][tid]);
        if (tid < 16) {
            #pragma unroll
            for (int t = 0; t < 16; t++) zacc1 += __uint_as_float(sk[t][256 + tid]);
        }
        #pragma unroll
        for (int k8 = 0; k8 < 16; k8 += 8) {
            uint32_t bf[8][2];
            #pragma unroll
            for (int j = 0; j < 8; j++) {
                bf[j][0] = sv[k8 + tg][j * 8 + g];
                bf[j][1] = sv[k8 + tg + 4][j * 8 + g];
            }
            #pragma unroll
            for (int ti = 0; ti < 3; ti++) {
                if (ti >= nt) break;
                int m0 = (ti == 0 ? tile0 : (ti == 1 ? tile1 : tile2)) * 16;
                uint32_t a[4];
                a[0] = sk[k8 + tg][m0 + g];
                a[1] = sk[k8 + tg][m0 + g + 8];
                a[2] = sk[k8 + tg + 4][m0 + g];
                a[3] = sk[k8 + tg + 4][m0 + g + 8];
                #pragma unroll
                for (int j = 0; j < 8; j++) mma_tf32(acc[ti][j], a, bf[j][0], bf[j][1]);
            }
        }
        __syncthreads();
    }

    float* Sb = g_S + ((size_t)bh * NCH + c) * (MM * DHD);
    #pragma unroll
    for (int ti = 0; ti < 3; ti++) {
        if (ti >= nt) break;
        int m0 = (ti == 0 ? tile0 : (ti == 1 ? tile1 : tile2)) * 16;
        int mlo = m0 + g, mhi = m0 + g + 8;
        #pragma unroll
        for (int j = 0; j < 8; j++) {
            int d = j * 8 + 2 * tg;
            if (mlo < MM) *(float2*)&Sb[(size_t)mlo * DHD + d] =
                make_float2(acc[ti][j][0], acc[ti][j][1]);
            if (mhi < MM) *(float2*)&Sb[(size_t)mhi * DHD + d] =
                make_float2(acc[ti][j][2], acc[ti][j][3]);
        }
    }
    float* zb = g_z + ((size_t)bh * NCH + c) * MM;
    zb[tid] = zacc0;
    if (tid < MM - 256) zb[256 + tid] = zacc1;
}

// ---------------- exclusive prefix over chunks ----------------
__global__ void scan_kernel(float* data, int per) {
    int gid = blockIdx.x * blockDim.x + threadIdx.x;
    if (gid >= BHT * per) return;
    int bh = gid / per, e = gid % per;
    size_t base = (size_t)bh * NCH * per + e;
    float run = 0.f;
    #pragma unroll 4
    for (int c = 0; c < NCH; c++) {
        size_t idx = base + (size_t)c * per;
        float cur = data[idx];
        data[idx] = run;
        run += cur;
    }
}

// ---------------- phase C (TF32 mma) ----------------
__global__ void __launch_bounds__(256) phaseC_kernel() {
    __shared__ uint32_t A_sh[64][68];
    __shared__ uint32_t wbuf[4608];
    __shared__ float zs[32];
    __shared__ float dred[4][64];
    __shared__ float den_sh[64];

    uint32_t (*qs)[36] = (uint32_t(*)[36])wbuf;
    uint32_t (*ks)[36] = (uint32_t(*)[36])(wbuf + 2304);
    uint32_t (*Vs)[68] = (uint32_t(*)[68])wbuf;
    uint32_t (*Ss)[68] = (uint32_t(*)[68])(wbuf + 2304);

    const int tid = threadIdx.x;
    const int wid = tid >> 5, lane = tid & 31;
    const int g = lane >> 2, tg = lane & 3;
    const int t0 = (wid & 3) * 16;
    const int n0 = (wid >> 2) * 32;
    const int c = blockIdx.x, bh = blockIdx.y;
    const int b = bh >> 3, h = bh & 7;
    const int l0 = c * CHUNK;
    const float* qb = g_qp + ((size_t)bh * LL + l0) * MM;
    const float* kb = g_kp + ((size_t)bh * LL + l0) * MM;
    const float* zb = g_z + ((size_t)bh * NCH + c) * MM;
    const float* Sb = g_S + ((size_t)bh * NCH + c) * (MM * DHD);

    float c1[4][4];
    #pragma unroll
    for (int j = 0; j < 4; j++)
        #pragma unroll
        for (int q = 0; q < 4; q++) c1[j][q] = 0.f;
    float dq = 0.f;
    const int dt = tid & 63, dslice = tid >> 6;

    for (int m0 = 0; m0 < 272; m0 += 32) {
        #pragma unroll 4
        for (int idx = tid; idx < 64 * 16; idx += 256) {
            int t = idx >> 4, m2 = (idx & 15) * 2;
            int m = m0 + m2;
            float2 qv = make_float2(0.f, 0.f), kv = make_float2(0.f, 0.f);
            if (m < MM) {
                qv = *(const float2*)&qb[(size_t)t * MM + m];
                kv = *(const float2*)&kb[(size_t)t * MM + m];
            }
            qs[t][m2] = f2tf(qv.x); qs[t][m2 + 1] = f2tf(qv.y);
            ks[t][m2] = f2tf(kv.x); ks[t][m2 + 1] = f2tf(kv.y);
        }
        if (tid < 32) zs[tid] = (m0 + tid < MM) ? zb[m0 + tid] : 0.f;
        __syncthreads();
        #pragma unroll
        for (int i = 0; i < 8; i++) {
            int mm = dslice * 8 + i;
            dq += __uint_as_float(qs[dt][mm]) * zs[mm];
        }
        #pragma unroll
        for (int k8 = 0; k8 < 32; k8 += 8) {
            uint32_t a[4];
            a[0] = qs[t0 + g][k8 + tg];
            a[1] = qs[t0 + g + 8][k8 + tg];
            a[2] = qs[t0 + g][k8 + tg + 4];
            a[3] = qs[t0 + g + 8][k8 + tg + 4];
            #pragma unroll
            for (int j = 0; j < 4; j++) {
                uint32_t b0 = ks[n0 + j * 8 + g][k8 + tg];
                uint32_t b1 = ks[n0 + j * 8 + g][k8 + tg + 4];
                mma_tf32(c1[j], a, b0, b1);
            }
        }
        __syncthreads();
    }
    dred[dslice][dt] = dq;

    {
        int ta = t0 + g, tb2 = t0 + g + 8;
        #pragma unroll
        for (int j = 0; j < 4; j++) {
            int s = n0 + j * 8 + 2 * tg;
            A_sh[ta][s]      = f2tf((s     <= ta)  ? c1[j][0] : 0.f);
            A_sh[ta][s + 1]  = f2tf((s + 1 <= ta)  ? c1[j][1] : 0.f);
            A_sh[tb2][s]     = f2tf((s     <= tb2) ? c1[j][2] : 0.f);
            A_sh[tb2][s + 1] = f2tf((s + 1 <= tb2) ? c1[j][3] : 0.f);
        }
    }
    __syncthreads();

    if (tid < 64) {
        float r = dred[0][tid] + dred[1][tid] + dred[2][tid] + dred[3][tid];
        #pragma unroll 8
        for (int s = 0; s < 64; s++) r += __uint_as_float(A_sh[tid][s]);
        den_sh[tid] = r;
    }

    {
        int t = tid >> 2, d16 = (tid & 3) * 16;
        const float* vr = &g_V[((size_t)(b * LL + l0 + t)) * DD + h * DHD + d16];
        #pragma unroll
        for (int q = 0; q < 4; q++) {
            float4 vv = *(const float4*)&vr[q * 4];
            Vs[t][d16 + q * 4]     = f2tf(vv.x);
            Vs[t][d16 + q * 4 + 1] = f2tf(vv.y);
            Vs[t][d16 + q * 4 + 2] = f2tf(vv.z);
            Vs[t][d16 + q * 4 + 3] = f2tf(vv.w);
        }
    }
    __syncthreads();

    float c2[4][4];
    #pragma unroll
    for (int j = 0; j < 4; j++)
        #pragma unroll
        for (int q = 0; q < 4; q++) c2[j][q] = 0.f;

    #pragma unroll
    for (int k8 = 0; k8 < 64; k8 += 8) {
        uint32_t a[4];
        a[0] = A_sh[t0 + g][k8 + tg];
        a[1] = A_sh[t0 + g + 8][k8 + tg];
        a[2] = A_sh[t0 + g][k8 + tg + 4];
        a[3] = A_sh[t0 + g + 8][k8 + tg + 4];
        #pragma unroll
        for (int j = 0; j < 4; j++) {
            uint32_t b0 = Vs[k8 + tg][n0 + j * 8 + g];
            uint32_t b1 = Vs[k8 + tg + 4][n0 + j * 8 + g];
            mma_tf32(c2[j], a, b0, b1);
        }
    }
    __syncthreads();

    for (int m0 = 0; m0 < 272; m0 += 32) {
        #pragma unroll 4
        for (int idx = tid; idx < 64 * 16; idx += 256) {
            int t = idx >> 4, m2 = (idx & 15) * 2;
            int m = m0 + m2;
            float2 qv = make_float2(0.f, 0.f);
            if (m < MM) qv = *(const float2*)&qb[(size_t)t * MM + m];
            qs[t][m2] = f2tf(qv.x); qs[t][m2 + 1] = f2tf(qv.y);
        }
        #pragma unroll 2
        for (int idx = tid; idx < 32 * 16; idx += 256) {
            int mm = idx >> 4, d4 = (idx & 15) * 4;
            int m = m0 + mm;
            float4 sv4 = make_float4(0.f, 0.f, 0.f, 0.f);
            if (m < MM) sv4 = *(const float4*)&Sb[(size_t)m * DHD + d4];
            Ss[mm][d4]     = f2tf(sv4.x);
            Ss[mm][d4 + 1] = f2tf(sv4.y);
            Ss[mm][d4 + 2] = f2tf(sv4.z);
            Ss[mm][d4 + 3] = f2tf(sv4.w);
        }
        __syncthreads();
        #pragma unroll
        for (int k8 = 0; k8 < 32; k8 += 8) {
            uint32_t a[4];
            a[0] = qs[t0 + g][k8 + tg];
            a[1] = qs[t0 + g + 8][k8 + tg];
            a[2] = qs[t0 + g][k8 + tg + 4];
            a[3] = qs[t0 + g + 8][k8 + tg + 4];
            #pragma unroll
            for (int j = 0; j < 4; j++) {
                uint32_t b0 = Ss[k8 + tg][n0 + j * 8 + g];
                uint32_t b1 = Ss[k8 + tg + 4][n0 + j * 8 + g];
                mma_tf32(c2[j], a, b0, b1);
            }
        }
        __syncthreads();
    }

    {
        int ta = t0 + g, tb2 = t0 + g + 8;
        float inva = 1.0f / den_sh[ta];
        float invb = 1.0f / den_sh[tb2];
        #pragma unroll
        for (int j = 0; j < 4; j++) {
            int d = n0 + j * 8 + 2 * tg;
            *(float2*)&g_ctx[((size_t)(b * LL + l0 + ta)) * DD + h * DHD + d] =
                make_float2(c2[j][0] * inva, c2[j][1] * inva);
            *(float2*)&g_ctx[((size_t)(b * LL + l0 + tb2)) * DD + h * DHD + d] =
                make_float2(c2[j][2] * invb, c2[j][3] * invb);
        }
    }
}

// ---------------- launch ----------------
extern "C" void kernel_launch(void* const* d_in, const int* in_sizes, int n_in,
                              void* d_out, int out_size) {
    const float* query = (const float*)d_in[0];
    const float* key   = (const float*)d_in[1];
    const float* value = (const float*)d_in[2];
    const float* Wq    = (const float*)d_in[3];
    const float* bq    = (const float*)d_in[4];
    const float* Wk    = (const float*)d_in[5];
    const float* bk    = (const float*)d_in[6];
    const float* Wv    = (const float*)d_in[7];
    const float* bv    = (const float*)d_in[8];
    const float* Wout  = (const float*)d_in[9];
    const float* bout  = (const float*)d_in[10];
    const float* RF    = (const float*)d_in[11];

    float *Qp, *Kp, *Vp, *hqp, *hkp, *qpp, *kpp, *Sp, *zp, *ctxp;
    cudaGetSymbolAddress((void**)&Qp,  g_Q);
    cudaGetSymbolAddress((void**)&Kp,  g_K);
    cudaGetSymbolAddress((void**)&Vp,  g_V);
    cudaGetSymbolAddress((void**)&hqp, g_hq);
    cudaGetSymbolAddress((void**)&hkp, g_hk);
    cudaGetSymbolAddress((void**)&qpp, g_qp);
    cudaGetSymbolAddress((void**)&kpp, g_kp);
    cudaGetSymbolAddress((void**)&Sp,  g_S);
    cudaGetSymbolAddress((void**)&zp,  g_z);
    cudaGetSymbolAddress((void**)&ctxp, g_ctx);

    dim3 gp(DD / 128, NROWS / 128, 3);
    tf32_gemm<<<gp, 256>>>(query, Wq, bq, Qp,
                           key,   Wk, bk, Kp,
                           value, Wv, bv, Vp);

    hq_kernel<<<NROWS, 256>>>(Qp, hqp);
    hq_kernel<<<NROWS, 256>>>(Kp, hkp);

    dim3 fg((MM + 63) / 64, NROWS / 128, HH);
    feat_gemm<<<fg, 256>>>(Qp, RF, hqp, qpp);
    feat_gemm<<<fg, 256>>>(Kp, RF, hkp, kpp);

    dim3 pg(NCH, BHT);
    phaseA_kernel<<<pg, 256>>>();

    int perS = MM * DHD;
    scan_kernel<<<(BHT * perS + 255) / 256, 256>>>(Sp, perS);
    scan_kernel<<<(BHT * MM + 255) / 256, 256>>>(zp, MM);

    phaseC_kernel<<<pg, 256>>>();

    dim3 go(DD / 128, NROWS / 128, 1);
    tf32_gemm<<<go, 256>>>(ctxp, Wout, bout, (float*)d_out,
                           ctxp, Wout, bout, (float*)d_out,
                           ctxp, Wout, bout, (float*)d_out);
}

// round 7
// speedup vs baseline: 1.8060x; 1.0428x over previous
#include <cuda_runtime.h>
#include <math.h>
#include <stdint.h>

// ---------------- problem constants ----------------
#define BB    2
#define LL    4096
#define DD    512
#define HH    8
#define DHD   64
#define MM    266
#define NROWS (BB*LL)        // 8192
#define CHUNK 64
#define NCH   (LL/CHUNK)     // 64
#define BHT   (BB*HH)        // 16

#define INV_S4      0.21022410381342863f   // 512^-0.25
#define INV_SQRT512 0.04419417382415922f   // 512^-0.5

// ---------------- scratch ----------------
__device__ float g_Q[NROWS*DD];
__device__ float g_K[NROWS*DD];
__device__ float g_V[NROWS*DD];
__device__ float g_hq[NROWS*HH];
__device__ float g_hk[NROWS*HH];
__device__ float g_qp[(size_t)BHT*LL*MM];
__device__ float g_kp[(size_t)BHT*LL*MM];
__device__ float g_S [(size_t)BHT*NCH*MM*DHD];
__device__ float g_z [(size_t)BHT*NCH*MM];
__device__ float g_ctx[NROWS*DD];

// ---------------- TF32 helpers ----------------
__device__ __forceinline__ uint32_t f2tf(float f) {
    uint32_t u;
    asm("cvt.rna.tf32.f32 %0, %1;" : "=r"(u) : "f"(f));
    return u;
}
__device__ __forceinline__ void mma_tf32(float* c, const uint32_t* a,
                                         uint32_t b0, uint32_t b1) {
    asm volatile(
        "mma.sync.aligned.m16n8k8.row.col.f32.tf32.tf32.f32 "
        "{%0,%1,%2,%3}, {%4,%5,%6,%7}, {%8,%9}, {%0,%1,%2,%3};"
        : "+f"(c[0]), "+f"(c[1]), "+f"(c[2]), "+f"(c[3])
        : "r"(a[0]), "r"(a[1]), "r"(a[2]), "r"(a[3]), "r"(b0), "r"(b1));
}

// ---------------- TF32 GEMM with register-prefetch pipelining ----------------
__global__ void __launch_bounds__(256, 2)
tf32_gemm(const float* __restrict__ A0, const float* __restrict__ W0,
          const float* __restrict__ bb0, float* __restrict__ C0,
          const float* __restrict__ A1, const float* __restrict__ W1,
          const float* __restrict__ bb1, float* __restrict__ C1,
          const float* __restrict__ A2, const float* __restrict__ W2,
          const float* __restrict__ bb2, float* __restrict__ C2) {
    __shared__ uint32_t As[128][36];
    __shared__ uint32_t Ws[128][36];

    const float* A; const float* W; const float* bias; float* C;
    if (blockIdx.z == 0)      { A = A0; W = W0; bias = bb0; C = C0; }
    else if (blockIdx.z == 1) { A = A1; W = W1; bias = bb1; C = C1; }
    else                      { A = A2; W = W2; bias = bb2; C = C2; }

    const int t = threadIdx.x;
    const int wid = t >> 5, lane = t & 31;
    const int warp_m = (wid & 3) * 32;
    const int warp_n = (wid >> 2) * 64;
    const int row0 = blockIdx.y * 128, col0 = blockIdx.x * 128;
    const int g = lane >> 2, tg = lane & 3;
    const int rl = t >> 3;          // 0..31 load row base
    const int ql = (t & 7) * 4;     // k offset 0..28

    float c[2][8][4];
    #pragma unroll
    for (int f = 0; f < 2; f++)
        #pragma unroll
        for (int j = 0; j < 8; j++)
            #pragma unroll
            for (int q = 0; q < 4; q++) c[f][j][q] = 0.f;

    float4 aR[4], wR[4];
    #pragma unroll
    for (int i = 0; i < 4; i++) {
        aR[i] = *(const float4*)&A[(size_t)(row0 + rl + i * 32) * DD + ql];
        wR[i] = *(const float4*)&W[(size_t)(col0 + rl + i * 32) * DD + ql];
    }
    #pragma unroll
    for (int i = 0; i < 4; i++) {
        *(uint4*)&As[rl + i * 32][ql] =
            make_uint4(f2tf(aR[i].x), f2tf(aR[i].y), f2tf(aR[i].z), f2tf(aR[i].w));
        *(uint4*)&Ws[rl + i * 32][ql] =
            make_uint4(f2tf(wR[i].x), f2tf(wR[i].y), f2tf(wR[i].z), f2tf(wR[i].w));
    }
    __syncthreads();

    for (int kt = 0; kt < DD / 32; kt++) {
        if (kt < DD / 32 - 1) {
            int ks = (kt + 1) * 32;
            #pragma unroll
            for (int i = 0; i < 4; i++) {
                aR[i] = *(const float4*)&A[(size_t)(row0 + rl + i * 32) * DD + ks + ql];
                wR[i] = *(const float4*)&W[(size_t)(col0 + rl + i * 32) * DD + ks + ql];
            }
        }
        #pragma unroll
        for (int k8 = 0; k8 < 32; k8 += 8) {
            uint32_t a[2][4];
            #pragma unroll
            for (int f = 0; f < 2; f++) {
                int m0 = warp_m + 16 * f;
                a[f][0] = As[m0 + g][k8 + tg];
                a[f][1] = As[m0 + g + 8][k8 + tg];
                a[f][2] = As[m0 + g][k8 + tg + 4];
                a[f][3] = As[m0 + g + 8][k8 + tg + 4];
            }
            #pragma unroll
            for (int j = 0; j < 8; j++) {
                uint32_t b0 = Ws[warp_n + 8 * j + g][k8 + tg];
                uint32_t b1 = Ws[warp_n + 8 * j + g][k8 + tg + 4];
                mma_tf32(c[0][j], a[0], b0, b1);
                mma_tf32(c[1][j], a[1], b0, b1);
            }
        }
        if (kt < DD / 32 - 1) {
            __syncthreads();
            #pragma unroll
            for (int i = 0; i < 4; i++) {
                *(uint4*)&As[rl + i * 32][ql] =
                    make_uint4(f2tf(aR[i].x), f2tf(aR[i].y), f2tf(aR[i].z), f2tf(aR[i].w));
                *(uint4*)&Ws[rl + i * 32][ql] =
                    make_uint4(f2tf(wR[i].x), f2tf(wR[i].y), f2tf(wR[i].z), f2tf(wR[i].w));
            }
            __syncthreads();
        }
    }

    #pragma unroll
    for (int f = 0; f < 2; f++) {
        int r0 = row0 + warp_m + 16 * f + g;
        #pragma unroll
        for (int j = 0; j < 8; j++) {
            int cidx = col0 + warp_n + 8 * j + 2 * tg;
            float bx = bias[cidx], by = bias[cidx + 1];
            float2 o0 = make_float2(c[f][j][0] + bx, c[f][j][1] + by);
            float2 o1 = make_float2(c[f][j][2] + bx, c[f][j][3] + by);
            *(float2*)&C[(size_t)r0 * DD + cidx] = o0;
            *(float2*)&C[(size_t)(r0 + 8) * DD + cidx] = o1;
        }
    }
}

// ---------------- per-(row,head) -0.5*||x/scale||^2 ----------------
__global__ void hq_kernel(const float* __restrict__ X, float* __restrict__ hout) {
    int row = blockIdx.x;
    int w = threadIdx.x >> 5, lane = threadIdx.x & 31;
    const float* xr = X + (size_t)row * DD + w * DHD;
    float2 v = *(const float2*)&xr[lane * 2];
    float s = v.x * v.x + v.y * v.y;
    #pragma unroll
    for (int off = 16; off; off >>= 1) s += __shfl_xor_sync(0xffffffffu, s, off);
    if (lane == 0) hout[(size_t)row * HH + w] = -0.5f * INV_SQRT512 * s;
}

// ---------------- feature map (TF32 mma, guard-free fast path) ----------------
__global__ void __launch_bounds__(256) feat_gemm(const float* __restrict__ X,
                                                 const float* __restrict__ RF,
                                                 const float* __restrict__ hv,
                                                 float* __restrict__ outp) {
    __shared__ uint32_t Xs[128][36];
    __shared__ uint32_t Rs[64][36];

    const int t = threadIdx.x;
    const int wid = t >> 5, lane = t & 31;
    const int g = lane >> 2, tg = lane & 3;
    const int warp_m = (wid & 3) * 32;
    const int warp_n = (wid >> 2) * 32;
    const int h  = blockIdx.z;
    const int r0 = blockIdx.y * 128;
    const int m0 = blockIdx.x * 64;
    const bool full = (m0 + 64 <= MM);   // tiles 0..3

    float c[2][4][4];
    #pragma unroll
    for (int f = 0; f < 2; f++)
        #pragma unroll
        for (int j = 0; j < 4; j++)
            #pragma unroll
            for (int q = 0; q < 4; q++) c[f][j][q] = 0.f;

    for (int kc = 0; kc < DHD; kc += 32) {
        #pragma unroll
        for (int i = 0; i < 4; i++) {
            int idx = t + i * 256;
            int r = idx >> 3, q = idx & 7;
            float4 xv = *(const float4*)&X[(size_t)(r0 + r) * DD + h * DHD + kc + q * 4];
            uint4 xu = make_uint4(f2tf(xv.x * INV_S4), f2tf(xv.y * INV_S4),
                                  f2tf(xv.z * INV_S4), f2tf(xv.w * INV_S4));
            *(uint4*)&Xs[r][q * 4] = xu;
        }
        if (full) {
            #pragma unroll
            for (int i = 0; i < 2; i++) {
                int idx = t + i * 256;
                int mr = idx >> 3, q = idx & 7;
                float4 rv = *(const float4*)&RF[(size_t)(m0 + mr) * DHD + kc + q * 4];
                *(uint4*)&Rs[mr][q * 4] =
                    make_uint4(f2tf(rv.x), f2tf(rv.y), f2tf(rv.z), f2tf(rv.w));
            }
        } else {
            #pragma unroll
            for (int i = 0; i < 2; i++) {
                int idx = t + i * 256;
                int mr = idx >> 3, q = idx & 7;
                float4 rv = make_float4(0.f, 0.f, 0.f, 0.f);
                if (m0 + mr < MM) rv = *(const float4*)&RF[(size_t)(m0 + mr) * DHD + kc + q * 4];
                *(uint4*)&Rs[mr][q * 4] =
                    make_uint4(f2tf(rv.x), f2tf(rv.y), f2tf(rv.z), f2tf(rv.w));
            }
        }
        __syncthreads();
        #pragma unroll
        for (int k8 = 0; k8 < 32; k8 += 8) {
            uint32_t a[2][4];
            #pragma unroll
            for (int f = 0; f < 2; f++) {
                int mw = warp_m + 16 * f;
                a[f][0] = Xs[mw + g][k8 + tg];
                a[f][1] = Xs[mw + g + 8][k8 + tg];
                a[f][2] = Xs[mw + g][k8 + tg + 4];
                a[f][3] = Xs[mw + g + 8][k8 + tg + 4];
            }
            #pragma unroll
            for (int j = 0; j < 4; j++) {
                uint32_t b0 = Rs[warp_n + 8 * j + g][k8 + tg];
                uint32_t b1 = Rs[warp_n + 8 * j + g][k8 + tg + 4];
                mma_tf32(c[0][j], a[0], b0, b1);
                mma_tf32(c[1][j], a[1], b0, b1);
            }
        }
        __syncthreads();
    }

    #pragma unroll
    for (int f = 0; f < 2; f++) {
        int ra = r0 + warp_m + 16 * f + g;
        int rb = ra + 8;
        float ha = hv[(size_t)ra * HH + h];
        float hb = hv[(size_t)rb * HH + h];
        int ba = ra >> 12, la = ra & 4095;
        int bb = rb >> 12, lb = rb & 4095;
        size_t basea = (((size_t)(ba * HH + h)) * LL + la) * MM;
        size_t baseb = (((size_t)(bb * HH + h)) * LL + lb) * MM;
        if (full) {
            #pragma unroll
            for (int j = 0; j < 4; j++) {
                int m = m0 + warp_n + 8 * j + 2 * tg;
                *(float2*)&outp[basea + m] =
                    make_float2(__expf(c[f][j][0] + ha), __expf(c[f][j][1] + ha));
                *(float2*)&outp[baseb + m] =
                    make_float2(__expf(c[f][j][2] + hb), __expf(c[f][j][3] + hb));
            }
        } else {
            #pragma unroll
            for (int j = 0; j < 4; j++) {
                int m = m0 + warp_n + 8 * j + 2 * tg;
                if (m < MM)     outp[basea + m]     = __expf(c[f][j][0] + ha);
                if (m + 1 < MM) outp[basea + m + 1] = __expf(c[f][j][1] + ha);
                if (m < MM)     outp[baseb + m]     = __expf(c[f][j][2] + hb);
                if (m + 1 < MM) outp[baseb + m + 1] = __expf(c[f][j][3] + hb);
            }
        }
    }
}

// ---------------- phase A (TF32 mma) ----------------
__global__ void __launch_bounds__(256) phaseA_kernel() {
    __shared__ uint32_t sk[16][276];
    __shared__ uint32_t sv[16][68];

    const int tid = threadIdx.x;
    const int wid = tid >> 5, lane = tid & 31;
    const int g = lane >> 2, tg = lane & 3;
    const int c = blockIdx.x, bh = blockIdx.y;
    const int b = bh >> 3, h = bh & 7;
    const int l0 = c * CHUNK;
    const float* kb = g_kp + ((size_t)bh * LL + l0) * MM;
    const float* vb = g_V + ((size_t)(b * LL + l0)) * DD + h * DHD;

    const int nt = (wid == 0) ? 3 : 2;
    int tile0 = wid, tile1 = wid + 8, tile2 = 16;

    float acc[3][8][4];
    #pragma unroll
    for (int ti = 0; ti < 3; ti++)
        #pragma unroll
        for (int j = 0; j < 8; j++)
            #pragma unroll
            for (int q = 0; q < 4; q++) acc[ti][j][q] = 0.f;
    float zacc0 = 0.f, zacc1 = 0.f;

    const int svt = tid >> 4, svd = (tid & 15) * 4;

    for (int t0 = 0; t0 < CHUNK; t0 += 16) {
        #pragma unroll 3
        for (int idx = tid; idx < 16 * 136; idx += 256) {
            int t = idx / 136, m2 = (idx % 136) * 2;
            float2 kv = make_float2(0.f, 0.f);
            if (m2 < MM) kv = *(const float2*)&kb[(size_t)(t0 + t) * MM + m2];
            sk[t][m2]     = f2tf(kv.x);
            sk[t][m2 + 1] = f2tf(kv.y);
        }
        {
            float4 vv = *(const float4*)&vb[(size_t)(t0 + svt) * DD + svd];
            sv[svt][svd]     = f2tf(vv.x);
            sv[svt][svd + 1] = f2tf(vv.y);
            sv[svt][svd + 2] = f2tf(vv.z);
            sv[svt][svd + 3] = f2tf(vv.w);
        }
        __syncthreads();
        #pragma unroll
        for (int t = 0; t < 16; t++) zacc0 += __uint_as_float(sk[t][tid]);
        if (tid < 16) {
            #pragma unroll
            for (int t = 0; t < 16; t++) zacc1 += __uint_as_float(sk[t][256 + tid]);
        }
        #pragma unroll
        for (int k8 = 0; k8 < 16; k8 += 8) {
            uint32_t bf[8][2];
            #pragma unroll
            for (int j = 0; j < 8; j++) {
                bf[j][0] = sv[k8 + tg][j * 8 + g];
                bf[j][1] = sv[k8 + tg + 4][j * 8 + g];
            }
            #pragma unroll
            for (int ti = 0; ti < 3; ti++) {
                if (ti >= nt) break;
                int m0 = (ti == 0 ? tile0 : (ti == 1 ? tile1 : tile2)) * 16;
                uint32_t a[4];
                a[0] = sk[k8 + tg][m0 + g];
                a[1] = sk[k8 + tg][m0 + g + 8];
                a[2] = sk[k8 + tg + 4][m0 + g];
                a[3] = sk[k8 + tg + 4][m0 + g + 8];
                #pragma unroll
                for (int j = 0; j < 8; j++) mma_tf32(acc[ti][j], a, bf[j][0], bf[j][1]);
            }
        }
        __syncthreads();
    }

    float* Sb = g_S + ((size_t)bh * NCH + c) * (MM * DHD);
    #pragma unroll
    for (int ti = 0; ti < 3; ti++) {
        if (ti >= nt) break;
        int m0 = (ti == 0 ? tile0 : (ti == 1 ? tile1 : tile2)) * 16;
        int mlo = m0 + g, mhi = m0 + g + 8;
        #pragma unroll
        for (int j = 0; j < 8; j++) {
            int d = j * 8 + 2 * tg;
            if (mlo < MM) *(float2*)&Sb[(size_t)mlo * DHD + d] =
                make_float2(acc[ti][j][0], acc[ti][j][1]);
            if (mhi < MM) *(float2*)&Sb[(size_t)mhi * DHD + d] =
                make_float2(acc[ti][j][2], acc[ti][j][3]);
        }
    }
    float* zb = g_z + ((size_t)bh * NCH + c) * MM;
    zb[tid] = zacc0;
    if (tid < MM - 256) zb[256 + tid] = zacc1;
}

// ---------------- exclusive prefix over chunks ----------------
__global__ void scan_kernel(float* data, int per) {
    int gid = blockIdx.x * blockDim.x + threadIdx.x;
    if (gid >= BHT * per) return;
    int bh = gid / per, e = gid % per;
    size_t base = (size_t)bh * NCH * per + e;
    float run = 0.f;
    #pragma unroll 4
    for (int c = 0; c < NCH; c++) {
        size_t idx = base + (size_t)c * per;
        float cur = data[idx];
        data[idx] = run;
        run += cur;
    }
}

// ---------------- phase C (TF32 mma) ----------------
__global__ void __launch_bounds__(256) phaseC_kernel() {
    __shared__ uint32_t A_sh[64][68];
    __shared__ uint32_t wbuf[4608];
    __shared__ float zs[32];
    __shared__ float dred[4][64];
    __shared__ float den_sh[64];

    uint32_t (*qs)[36] = (uint32_t(*)[36])wbuf;
    uint32_t (*ks)[36] = (uint32_t(*)[36])(wbuf + 2304);
    uint32_t (*Vs)[68] = (uint32_t(*)[68])wbuf;
    uint32_t (*Ss)[68] = (uint32_t(*)[68])(wbuf + 2304);

    const int tid = threadIdx.x;
    const int wid = tid >> 5, lane = tid & 31;
    const int g = lane >> 2, tg = lane & 3;
    const int t0 = (wid & 3) * 16;
    const int n0 = (wid >> 2) * 32;
    const int c = blockIdx.x, bh = blockIdx.y;
    const int b = bh >> 3, h = bh & 7;
    const int l0 = c * CHUNK;
    const float* qb = g_qp + ((size_t)bh * LL + l0) * MM;
    const float* kb = g_kp + ((size_t)bh * LL + l0) * MM;
    const float* zb = g_z + ((size_t)bh * NCH + c) * MM;
    const float* Sb = g_S + ((size_t)bh * NCH + c) * (MM * DHD);

    float c1[4][4];
    #pragma unroll
    for (int j = 0; j < 4; j++)
        #pragma unroll
        for (int q = 0; q < 4; q++) c1[j][q] = 0.f;
    float dq = 0.f;
    const int dt = tid & 63, dslice = tid >> 6;

    for (int m0 = 0; m0 < 272; m0 += 32) {
        #pragma unroll 4
        for (int idx = tid; idx < 64 * 16; idx += 256) {
            int t = idx >> 4, m2 = (idx & 15) * 2;
            int m = m0 + m2;
            float2 qv = make_float2(0.f, 0.f), kv = make_float2(0.f, 0.f);
            if (m < MM) {
                qv = *(const float2*)&qb[(size_t)t * MM + m];
                kv = *(const float2*)&kb[(size_t)t * MM + m];
            }
            qs[t][m2] = f2tf(qv.x); qs[t][m2 + 1] = f2tf(qv.y);
            ks[t][m2] = f2tf(kv.x); ks[t][m2 + 1] = f2tf(kv.y);
        }
        if (tid < 32) zs[tid] = (m0 + tid < MM) ? zb[m0 + tid] : 0.f;
        __syncthreads();
        #pragma unroll
        for (int i = 0; i < 8; i++) {
            int mm = dslice * 8 + i;
            dq += __uint_as_float(qs[dt][mm]) * zs[mm];
        }
        #pragma unroll
        for (int k8 = 0; k8 < 32; k8 += 8) {
            uint32_t a[4];
            a[0] = qs[t0 + g][k8 + tg];
            a[1] = qs[t0 + g + 8][k8 + tg];
            a[2] = qs[t0 + g][k8 + tg + 4];
            a[3] = qs[t0 + g + 8][k8 + tg + 4];
            #pragma unroll
            for (int j = 0; j < 4; j++) {
                uint32_t b0 = ks[n0 + j * 8 + g][k8 + tg];
                uint32_t b1 = ks[n0 + j * 8 + g][k8 + tg + 4];
                mma_tf32(c1[j], a, b0, b1);
            }
        }
        __syncthreads();
    }
    dred[dslice][dt] = dq;

    {
        int ta = t0 + g, tb2 = t0 + g + 8;
        #pragma unroll
        for (int j = 0; j < 4; j++) {
            int s = n0 + j * 8 + 2 * tg;
            A_sh[ta][s]      = f2tf((s     <= ta)  ? c1[j][0] : 0.f);
            A_sh[ta][s + 1]  = f2tf((s + 1 <= ta)  ? c1[j][1] : 0.f);
            A_sh[tb2][s]     = f2tf((s     <= tb2) ? c1[j][2] : 0.f);
            A_sh[tb2][s + 1] = f2tf((s + 1 <= tb2) ? c1[j][3] : 0.f);
        }
    }
    __syncthreads();

    if (tid < 64) {
        float r = dred[0][tid] + dred[1][tid] + dred[2][tid] + dred[3][tid];
        #pragma unroll 8
        for (int s = 0; s < 64; s++) r += __uint_as_float(A_sh[tid][s]);
        den_sh[tid] = r;
    }

    {
        int t = tid >> 2, d16 = (tid & 3) * 16;
        const float* vr = &g_V[((size_t)(b * LL + l0 + t)) * DD + h * DHD + d16];
        #pragma unroll
        for (int q = 0; q < 4; q++) {
            float4 vv = *(const float4*)&vr[q * 4];
            Vs[t][d16 + q * 4]     = f2tf(vv.x);
            Vs[t][d16 + q * 4 + 1] = f2tf(vv.y);
            Vs[t][d16 + q * 4 + 2] = f2tf(vv.z);
            Vs[t][d16 + q * 4 + 3] = f2tf(vv.w);
        }
    }
    __syncthreads();

    float c2[4][4];
    #pragma unroll
    for (int j = 0; j < 4; j++)
        #pragma unroll
        for (int q = 0; q < 4; q++) c2[j][q] = 0.f;

    #pragma unroll
    for (int k8 = 0; k8 < 64; k8 += 8) {
        uint32_t a[4];
        a[0] = A_sh[t0 + g][k8 + tg];
        a[1] = A_sh[t0 + g + 8][k8 + tg];
        a[2] = A_sh[t0 + g][k8 + tg + 4];
        a[3] = A_sh[t0 + g + 8][k8 + tg + 4];
        #pragma unroll
        for (int j = 0; j < 4; j++) {
            uint32_t b0 = Vs[k8 + tg][n0 + j * 8 + g];
            uint32_t b1 = Vs[k8 + tg + 4][n0 + j * 8 + g];
            mma_tf32(c2[j], a, b0, b1);
        }
    }
    __syncthreads();

    for (int m0 = 0; m0 < 272; m0 += 32) {
        #pragma unroll 4
        for (int idx = tid; idx < 64 * 16; idx += 256) {
            int t = idx >> 4, m2 = (idx & 15) * 2;
            int m = m0 + m2;
            float2 qv = make_float2(0.f, 0.f);
            if (m < MM) qv = *(const float2*)&qb[(size_t)t * MM + m];
            qs[t][m2] = f2tf(qv.x); qs[t][m2 + 1] = f2tf(qv.y);
        }
        #pragma unroll 2
        for (int idx = tid; idx < 32 * 16; idx += 256) {
            int mm = idx >> 4, d4 = (idx & 15) * 4;
            int m = m0 + mm;
            float4 sv4 = make_float4(0.f, 0.f, 0.f, 0.f);
            if (m < MM) sv4 = *(const float4*)&Sb[(size_t)m * DHD + d4];
            Ss[mm][d4]     = f2tf(sv4.x);
            Ss[mm][d4 + 1] = f2tf(sv4.y);
            Ss[mm][d4 + 2] = f2tf(sv4.z);
            Ss[mm][d4 + 3] = f2tf(sv4.w);
        }
        __syncthreads();
        #pragma unroll
        for (int k8 = 0; k8 < 32; k8 += 8) {
            uint32_t a[4];
            a[0] = qs[t0 + g][k8 + tg];
            a[1] = qs[t0 + g + 8][k8 + tg];
            a[2] = qs[t0 + g][k8 + tg + 4];
            a[3] = qs[t0 + g + 8][k8 + tg + 4];
            #pragma unroll
            for (int j = 0; j < 4; j++) {
                uint32_t b0 = Ss[k8 + tg][n0 + j * 8 + g];
                uint32_t b1 = Ss[k8 + tg + 4][n0 + j * 8 + g];
                mma_tf32(c2[j], a, b0, b1);
            }
        }
        __syncthreads();
    }

    {
        int ta = t0 + g, tb2 = t0 + g + 8;
        float inva = 1.0f / den_sh[ta];
        float invb = 1.0f / den_sh[tb2];
        #pragma unroll
        for (int j = 0; j < 4; j++) {
            int d = n0 + j * 8 + 2 * tg;
            *(float2*)&g_ctx[((size_t)(b * LL + l0 + ta)) * DD + h * DHD + d] =
                make_float2(c2[j][0] * inva, c2[j][1] * inva);
            *(float2*)&g_ctx[((size_t)(b * LL + l0 + tb2)) * DD + h * DHD + d] =
                make_float2(c2[j][2] * invb, c2[j][3] * invb);
        }
    }
}

// ---------------- launch ----------------
extern "C" void kernel_launch(void* const* d_in, const int* in_sizes, int n_in,
                              void* d_out, int out_size) {
    const float* query = (const float*)d_in[0];
    const float* key   = (const float*)d_in[1];
    const float* value = (const float*)d_in[2];
    const float* Wq    = (const float*)d_in[3];
    const float* bq    = (const float*)d_in[4];
    const float* Wk    = (const float*)d_in[5];
    const float* bk    = (const float*)d_in[6];
    const float* Wv    = (const float*)d_in[7];
    const float* bv    = (const float*)d_in[8];
    const float* Wout  = (const float*)d_in[9];
    const float* bout  = (const float*)d_in[10];
    const float* RF    = (const float*)d_in[11];

    float *Qp, *Kp, *Vp, *hqp, *hkp, *qpp, *kpp, *Sp, *zp, *ctxp;
    cudaGetSymbolAddress((void**)&Qp,  g_Q);
    cudaGetSymbolAddress((void**)&Kp,  g_K);
    cudaGetSymbolAddress((void**)&Vp,  g_V);
    cudaGetSymbolAddress((void**)&hqp, g_hq);
    cudaGetSymbolAddress((void**)&hkp, g_hk);
    cudaGetSymbolAddress((void**)&qpp, g_qp);
    cudaGetSymbolAddress((void**)&kpp, g_kp);
    cudaGetSymbolAddress((void**)&Sp,  g_S);
    cudaGetSymbolAddress((void**)&zp,  g_z);
    cudaGetSymbolAddress((void**)&ctxp, g_ctx);

    dim3 gp(DD / 128, NROWS / 128, 3);
    tf32_gemm<<<gp, 256>>>(query, Wq, bq, Qp,
                           key,   Wk, bk, Kp,
                           value, Wv, bv, Vp);

    hq_kernel<<<NROWS, 256>>>(Qp, hqp);
    hq_kernel<<<NROWS, 256>>>(Kp, hkp);

    dim3 fg((MM + 63) / 64, NROWS / 128, HH);
    feat_gemm<<<fg, 256>>>(Qp, RF, hqp, qpp);
    feat_gemm<<<fg, 256>>>(Kp, RF, hkp, kpp);

    dim3 pg(NCH, BHT);
    phaseA_kernel<<<pg, 256>>>();

    int perS = MM * DHD;
    scan_kernel<<<(BHT * perS + 255) / 256, 256>>>(Sp, perS);
    scan_kernel<<<(BHT * MM + 255) / 256, 256>>>(zp, MM);

    phaseC_kernel<<<pg, 256>>>();

    dim3 go(DD / 128, NROWS / 128, 1);
    tf32_gemm<<<go, 256>>>(ctxp, Wout, bout, (float*)d_out,
                           ctxp, Wout, bout, (float*)d_out,
                           ctxp, Wout, bout, (float*)d_out);
}